// round 6
// baseline (speedup 1.0000x reference)
#include <cuda_runtime.h>
#include <cuda_bf16.h>
#include <math.h>
#include <cstdint>

// Fixed shapes for HyperbolicMLR_33045478375870
#define BDIM 4096
#define DDIM 1024
#define CDIM 4096
#define EPSV 1e-15f
#define MAXN 0.99999f   // (1 - 1e-5)/sqrt(c), c = 1

// ---------------------------------------------------------------------------
// Device scratch (no allocations allowed)
// ---------------------------------------------------------------------------
__device__ __nv_bfloat16 g_xhi[(size_t)BDIM * DDIM];
__device__ __nv_bfloat16 g_phi[(size_t)CDIM * DDIM];
__device__ __nv_bfloat16 g_ahi[(size_t)CDIM * DDIM];
__device__ float g_x2[BDIM];
__device__ float g_p2[CDIM];
__device__ float g_pa[CDIM];
__device__ float g_an[CDIM];

// ---------------------------------------------------------------------------
__device__ __forceinline__ uint32_t smem_u32(const void* p) {
    uint32_t a;
    asm("{ .reg .u64 t; cvta.to.shared.u64 t, %1; cvt.u32.u64 %0, t; }"
        : "=r"(a) : "l"(p));
    return a;
}

#define LDSM4(r, addr) \
    asm volatile("ldmatrix.sync.aligned.m8n8.x4.shared.b16 {%0,%1,%2,%3}, [%4];" \
                 : "=r"((r)[0]), "=r"((r)[1]), "=r"((r)[2]), "=r"((r)[3]) \
                 : "r"(addr))

#define MMA16816(c, a, b0, b1) \
    asm volatile("mma.sync.aligned.m16n8k16.row.col.f32.bf16.bf16.f32 " \
                 "{%0,%1,%2,%3},{%4,%5,%6,%7},{%8,%9},{%0,%1,%2,%3};" \
                 : "+f"((c)[0]), "+f"((c)[1]), "+f"((c)[2]), "+f"((c)[3]) \
                 : "r"((a)[0]), "r"((a)[1]), "r"((a)[2]), "r"((a)[3]), \
                   "r"(b0), "r"(b1))

#define CP_ASYNC16(dst, src) \
    asm volatile("cp.async.cg.shared.global [%0], [%1], 16;" \
                 :: "r"(dst), "l"(__cvta_generic_to_global(src)))

// ---------------------------------------------------------------------------
// Merged prep kernel: blocks [0, BDIM) project x rows; blocks [BDIM, BDIM+CDIM)
// compute class stats + bf16 casts. float4-vectorized (1024 floats / 256 thr).
// ---------------------------------------------------------------------------
__global__ __launch_bounds__(256) void prep_kernel(const float* __restrict__ x,
                                                   const float* __restrict__ a,
                                                   const float* __restrict__ p) {
    const int blk = blockIdx.x;
    const int tid = threadIdx.x;
    __shared__ float red[3][8];

    if (blk < BDIM) {
        const int b = blk;
        const float4 v = ((const float4*)(x + (size_t)b * DDIM))[tid];
        float s = v.x * v.x + v.y * v.y + v.z * v.z + v.w * v.w;
        #pragma unroll
        for (int o = 16; o > 0; o >>= 1) s += __shfl_xor_sync(0xFFFFFFFFu, s, o);
        if ((tid & 31) == 0) red[0][tid >> 5] = s;
        __syncthreads();
        __shared__ float sh_scale;
        if (tid == 0) {
            float tot = 0.f;
            #pragma unroll
            for (int w = 0; w < 8; w++) tot += red[0][w];
            float xn = fmaxf(sqrtf(tot), EPSV);
            float scale = (xn > MAXN) ? (MAXN / xn) : 1.0f;
            sh_scale = scale;
            g_x2[b] = tot * scale * scale;
        }
        __syncthreads();
        const float sc = sh_scale;
        __nv_bfloat162 o0 = {__float2bfloat16(v.x * sc), __float2bfloat16(v.y * sc)};
        __nv_bfloat162 o1 = {__float2bfloat16(v.z * sc), __float2bfloat16(v.w * sc)};
        ((__nv_bfloat162*)(g_xhi + (size_t)b * DDIM))[tid * 2]     = o0;
        ((__nv_bfloat162*)(g_xhi + (size_t)b * DDIM))[tid * 2 + 1] = o1;
    } else {
        const int c = blk - BDIM;
        const float4 pv = ((const float4*)(p + (size_t)c * DDIM))[tid];
        const float4 av = ((const float4*)(a + (size_t)c * DDIM))[tid];
        float sp2 = pv.x * pv.x + pv.y * pv.y + pv.z * pv.z + pv.w * pv.w;
        float spa = pv.x * av.x + pv.y * av.y + pv.z * av.z + pv.w * av.w;
        float sa2 = av.x * av.x + av.y * av.y + av.z * av.z + av.w * av.w;
        __nv_bfloat162 p0 = {__float2bfloat16(pv.x), __float2bfloat16(pv.y)};
        __nv_bfloat162 p1 = {__float2bfloat16(pv.z), __float2bfloat16(pv.w)};
        __nv_bfloat162 a0 = {__float2bfloat16(av.x), __float2bfloat16(av.y)};
        __nv_bfloat162 a1 = {__float2bfloat16(av.z), __float2bfloat16(av.w)};
        ((__nv_bfloat162*)(g_phi + (size_t)c * DDIM))[tid * 2]     = p0;
        ((__nv_bfloat162*)(g_phi + (size_t)c * DDIM))[tid * 2 + 1] = p1;
        ((__nv_bfloat162*)(g_ahi + (size_t)c * DDIM))[tid * 2]     = a0;
        ((__nv_bfloat162*)(g_ahi + (size_t)c * DDIM))[tid * 2 + 1] = a1;
        #pragma unroll
        for (int o = 16; o > 0; o >>= 1) {
            sp2 += __shfl_xor_sync(0xFFFFFFFFu, sp2, o);
            spa += __shfl_xor_sync(0xFFFFFFFFu, spa, o);
            sa2 += __shfl_xor_sync(0xFFFFFFFFu, sa2, o);
        }
        if ((tid & 31) == 0) {
            red[0][tid >> 5] = sp2; red[1][tid >> 5] = spa; red[2][tid >> 5] = sa2;
        }
        __syncthreads();
        if (tid == 0) {
            float t0 = 0.f, t1 = 0.f, t2 = 0.f;
            #pragma unroll
            for (int w = 0; w < 8; w++) { t0 += red[0][w]; t1 += red[1][w]; t2 += red[2][w]; }
            g_p2[c] = t0; g_pa[c] = t1; g_an[c] = sqrtf(t2);
        }
    }
}

// ---------------------------------------------------------------------------
// Epilogue math: 1 MUFU (rsqrt), no division, no log.
// ---------------------------------------------------------------------------
__device__ __forceinline__ float hyp_logit(float px, float xa, float x2,
                                           float p2, float pa, float an) {
    const float A   = 1.0f - 2.0f * px + x2;
    const float Bc  = 1.0f - p2;
    const float den = fmaxf(fmaf(x2, p2, fmaf(-2.0f, px, 1.0f)), EPSV);
    const float w   = fmaxf(fmaf(A * A, p2, fmaf(Bc * Bc, x2, -2.0f * A * Bc * px)), 0.0f);
    const float u   = fmaf(Bc, xa, -A * pa);
    const float N   = 2.0f * u * den;
    const float D   = fmaf(den, den, w) * an;
    const float z   = N * rsqrtf(fmaf(N, N, D * D));
    const float t   = z * z;
    float s = 1.0f / 25.0f;
    s = fmaf(s, t, 1.0f / 23.0f); s = fmaf(s, t, 1.0f / 21.0f);
    s = fmaf(s, t, 1.0f / 19.0f); s = fmaf(s, t, 1.0f / 17.0f);
    s = fmaf(s, t, 1.0f / 15.0f); s = fmaf(s, t, 1.0f / 13.0f);
    s = fmaf(s, t, 1.0f / 11.0f); s = fmaf(s, t, 1.0f / 9.0f);
    s = fmaf(s, t, 1.0f / 7.0f);  s = fmaf(s, t, 1.0f / 5.0f);
    s = fmaf(s, t, 1.0f / 3.0f);  s = fmaf(s, t, 1.0f);
    return -z * s;
}

// ---------------------------------------------------------------------------
// Main kernel: dual pure-bf16 GEMM via mma.sync + fused epilogue
//   CTA 128x128, 512 threads (16 warps: 2 m x 8 n), warp tile 64x16.
//   BK=64, 4-stage cp.async pipeline, 3 smem tiles/stage, ROWB=144
//   (row stride 36 words == 4-bank shift per row -> conflict-free ldmatrix).
// ---------------------------------------------------------------------------
#define BM 128
#define BN 128
#define BK 64
#define NKIT (DDIM / BK)          // 16
#define NSTG 4
#define ROWB 144                  // 128 data + 16 pad
#define TILEB (128 * ROWB)        // 18432
#define STAGEB (3 * TILEB)        // 55296
#define SMEM_NEED (NSTG * STAGEB) // 221184

__global__ __launch_bounds__(512, 1) void mlr_mma_kernel(float* __restrict__ out) {
    extern __shared__ char sm[];
    const uint32_t sb = smem_u32(sm);
    const int tid  = threadIdx.x;
    const int wid  = tid >> 5;
    const int lane = tid & 31;
    const int wn = wid & 7;        // warp col (class):  8 x 16
    const int wm = wid >> 3;       // warp row (batch):  2 x 64
    const int cb = blockIdx.x * BN;
    const int rb = blockIdx.y * BM;

    const __nv_bfloat16* srcs[3] = {
        g_xhi + (size_t)rb * DDIM,
        g_phi + (size_t)cb * DDIM,
        g_ahi + (size_t)cb * DDIM
    };

    // cp.async mapping: 512 threads, 2 rows/thread/tile (rows lr and lr+64)
    const int lr = tid >> 3, lch = tid & 7;
    const uint32_t dA = lr * ROWB + lch * 16;
    const uint32_t dB = (lr + 64) * ROWB + lch * 16;
    const size_t  sA_ = (size_t)lr * DDIM + lch * 8;
    const size_t  sB_ = (size_t)(lr + 64) * DDIM + lch * 8;

    // ldmatrix lane mappings
    const int a_r = lane & 15;
    const int a_c = lane >> 4;
    const int b_r = (lane & 7) | ((lane & 16) >> 1);
    const int b_h = (lane >> 3) & 1;
    const uint32_t smA = (wm * 64 + a_r) * ROWB + a_c * 16;
    const uint32_t smB = (wn * 16 + b_r) * ROWB + b_h * 16;

    float cP[4][2][4];
    float cA[4][2][4];
    #pragma unroll
    for (int mt = 0; mt < 4; mt++)
        #pragma unroll
        for (int nt = 0; nt < 2; nt++)
            #pragma unroll
            for (int i = 0; i < 4; i++) { cP[mt][nt][i] = 0.f; cA[mt][nt][i] = 0.f; }

    // prologue: stages 0..2
    #pragma unroll
    for (int s = 0; s < NSTG - 1; s++) {
        const uint32_t db = sb + s * STAGEB;
        const size_t ko = (size_t)s * BK;
        #pragma unroll
        for (int t = 0; t < 3; t++) {
            CP_ASYNC16(db + t * TILEB + dA, srcs[t] + sA_ + ko);
            CP_ASYNC16(db + t * TILEB + dB, srcs[t] + sB_ + ko);
        }
        asm volatile("cp.async.commit_group;" ::: "memory");
    }

    for (int k = 0; k < NKIT; k++) {
        asm volatile("cp.async.wait_group %0;" :: "n"(NSTG - 2) : "memory");
        __syncthreads();

        if (k + NSTG - 1 < NKIT) {
            const uint32_t db = sb + ((k + NSTG - 1) & (NSTG - 1)) * STAGEB;
            const size_t ko = (size_t)(k + NSTG - 1) * BK;
            #pragma unroll
            for (int t = 0; t < 3; t++) {
                CP_ASYNC16(db + t * TILEB + dA, srcs[t] + sA_ + ko);
                CP_ASYNC16(db + t * TILEB + dB, srcs[t] + sB_ + ko);
            }
        }
        asm volatile("cp.async.commit_group;" ::: "memory");

        const uint32_t st = sb + (k & (NSTG - 1)) * STAGEB;
        #pragma unroll
        for (int ks = 0; ks < 4; ks++) {
            const uint32_t kofs = ks * 32;   // 16 bf16 = 32 bytes along K
            uint32_t bp[4], ba[4];
            LDSM4(bp, st + 1 * TILEB + smB + kofs);
            LDSM4(ba, st + 2 * TILEB + smB + kofs);
            uint32_t xh[4][4];
            #pragma unroll
            for (int mt = 0; mt < 4; mt++)
                LDSM4(xh[mt], st + 0 * TILEB + smA + mt * 16 * ROWB + kofs);
            #pragma unroll
            for (int mt = 0; mt < 4; mt++) {
                #pragma unroll
                for (int nt = 0; nt < 2; nt++) {
                    MMA16816(cP[mt][nt], xh[mt], bp[nt * 2], bp[nt * 2 + 1]);
                    MMA16816(cA[mt][nt], xh[mt], ba[nt * 2], ba[nt * 2 + 1]);
                }
            }
        }
    }

    // epilogue
    const int g  = lane >> 2;
    const int tg = lane & 3;
    #pragma unroll
    for (int mt = 0; mt < 4; mt++) {
        #pragma unroll
        for (int h = 0; h < 2; h++) {
            const int row = rb + wm * 64 + mt * 16 + h * 8 + g;
            const float x2 = g_x2[row];
            float* orow = out + (size_t)row * CDIM + cb + wn * 16;
            #pragma unroll
            for (int nt = 0; nt < 2; nt++) {
                const int col = cb + wn * 16 + nt * 8 + tg * 2;
                float2 r;
                r.x = hyp_logit(cP[mt][nt][2 * h],     cA[mt][nt][2 * h],     x2,
                                g_p2[col],     g_pa[col],     g_an[col]);
                r.y = hyp_logit(cP[mt][nt][2 * h + 1], cA[mt][nt][2 * h + 1], x2,
                                g_p2[col + 1], g_pa[col + 1], g_an[col + 1]);
                *(float2*)(orow + nt * 8 + tg * 2) = r;
            }
        }
    }
}

// ---------------------------------------------------------------------------
extern "C" void kernel_launch(void* const* d_in, const int* in_sizes, int n_in,
                              void* d_out, int out_size) {
    const float* x = (const float*)d_in[0];
    const float* a = (const float*)d_in[1];
    const float* p = (const float*)d_in[2];
    float* out = (float*)d_out;

    cudaFuncSetAttribute(mlr_mma_kernel,
                         cudaFuncAttributeMaxDynamicSharedMemorySize, SMEM_NEED);

    prep_kernel<<<BDIM + CDIM, 256>>>(x, a, p);
    dim3 grid(CDIM / BN, BDIM / BM);
    mlr_mma_kernel<<<grid, 512, SMEM_NEED>>>(out);
}

// round 7
// speedup vs baseline: 1.0300x; 1.0300x over previous
#include <cuda_runtime.h>
#include <cuda_bf16.h>
#include <math.h>
#include <cstdint>

// Fixed shapes for HyperbolicMLR_33045478375870
#define BDIM 4096
#define DDIM 1024
#define CDIM 4096
#define EPSV 1e-15f
#define MAXN 0.99999f   // (1 - 1e-5)/sqrt(c), c = 1

// ---------------------------------------------------------------------------
// Device scratch (no allocations allowed)
// ---------------------------------------------------------------------------
__device__ __nv_bfloat16 g_xhi[(size_t)BDIM * DDIM];
__device__ __nv_bfloat16 g_phi[(size_t)CDIM * DDIM];
__device__ __nv_bfloat16 g_ahi[(size_t)CDIM * DDIM];
__device__ float g_x2[BDIM];
__device__ float g_p2[CDIM];
__device__ float g_pa[CDIM];
__device__ float g_an[CDIM];

// ---------------------------------------------------------------------------
__device__ __forceinline__ uint32_t smem_u32(const void* p) {
    uint32_t a;
    asm("{ .reg .u64 t; cvta.to.shared.u64 t, %1; cvt.u32.u64 %0, t; }"
        : "=r"(a) : "l"(p));
    return a;
}

#define LDSM4(r, addr) \
    asm volatile("ldmatrix.sync.aligned.m8n8.x4.shared.b16 {%0,%1,%2,%3}, [%4];" \
                 : "=r"((r)[0]), "=r"((r)[1]), "=r"((r)[2]), "=r"((r)[3]) \
                 : "r"(addr))

#define MMA16816(c, a, b0, b1) \
    asm volatile("mma.sync.aligned.m16n8k16.row.col.f32.bf16.bf16.f32 " \
                 "{%0,%1,%2,%3},{%4,%5,%6,%7},{%8,%9},{%0,%1,%2,%3};" \
                 : "+f"((c)[0]), "+f"((c)[1]), "+f"((c)[2]), "+f"((c)[3]) \
                 : "r"((a)[0]), "r"((a)[1]), "r"((a)[2]), "r"((a)[3]), \
                   "r"(b0), "r"(b1))

#define CP_ASYNC16(dst, src) \
    asm volatile("cp.async.cg.shared.global [%0], [%1], 16;" \
                 :: "r"(dst), "l"(__cvta_generic_to_global(src)))

// ---------------------------------------------------------------------------
// Merged prep kernel: blocks [0, BDIM) project x rows; blocks [BDIM, BDIM+CDIM)
// compute class stats + bf16 casts. float4-vectorized.
// ---------------------------------------------------------------------------
__global__ __launch_bounds__(256) void prep_kernel(const float* __restrict__ x,
                                                   const float* __restrict__ a,
                                                   const float* __restrict__ p) {
    const int blk = blockIdx.x;
    const int tid = threadIdx.x;
    __shared__ float red[3][8];

    if (blk < BDIM) {
        const int b = blk;
        const float4 v = ((const float4*)(x + (size_t)b * DDIM))[tid];
        float s = v.x * v.x + v.y * v.y + v.z * v.z + v.w * v.w;
        #pragma unroll
        for (int o = 16; o > 0; o >>= 1) s += __shfl_xor_sync(0xFFFFFFFFu, s, o);
        if ((tid & 31) == 0) red[0][tid >> 5] = s;
        __syncthreads();
        __shared__ float sh_scale;
        if (tid == 0) {
            float tot = 0.f;
            #pragma unroll
            for (int w = 0; w < 8; w++) tot += red[0][w];
            float xn = fmaxf(sqrtf(tot), EPSV);
            float scale = (xn > MAXN) ? (MAXN / xn) : 1.0f;
            sh_scale = scale;
            g_x2[b] = tot * scale * scale;
        }
        __syncthreads();
        const float sc = sh_scale;
        __nv_bfloat162 o0 = {__float2bfloat16(v.x * sc), __float2bfloat16(v.y * sc)};
        __nv_bfloat162 o1 = {__float2bfloat16(v.z * sc), __float2bfloat16(v.w * sc)};
        ((__nv_bfloat162*)(g_xhi + (size_t)b * DDIM))[tid * 2]     = o0;
        ((__nv_bfloat162*)(g_xhi + (size_t)b * DDIM))[tid * 2 + 1] = o1;
    } else {
        const int c = blk - BDIM;
        const float4 pv = ((const float4*)(p + (size_t)c * DDIM))[tid];
        const float4 av = ((const float4*)(a + (size_t)c * DDIM))[tid];
        float sp2 = pv.x * pv.x + pv.y * pv.y + pv.z * pv.z + pv.w * pv.w;
        float spa = pv.x * av.x + pv.y * av.y + pv.z * av.z + pv.w * av.w;
        float sa2 = av.x * av.x + av.y * av.y + av.z * av.z + av.w * av.w;
        __nv_bfloat162 p0 = {__float2bfloat16(pv.x), __float2bfloat16(pv.y)};
        __nv_bfloat162 p1 = {__float2bfloat16(pv.z), __float2bfloat16(pv.w)};
        __nv_bfloat162 a0 = {__float2bfloat16(av.x), __float2bfloat16(av.y)};
        __nv_bfloat162 a1 = {__float2bfloat16(av.z), __float2bfloat16(av.w)};
        ((__nv_bfloat162*)(g_phi + (size_t)c * DDIM))[tid * 2]     = p0;
        ((__nv_bfloat162*)(g_phi + (size_t)c * DDIM))[tid * 2 + 1] = p1;
        ((__nv_bfloat162*)(g_ahi + (size_t)c * DDIM))[tid * 2]     = a0;
        ((__nv_bfloat162*)(g_ahi + (size_t)c * DDIM))[tid * 2 + 1] = a1;
        #pragma unroll
        for (int o = 16; o > 0; o >>= 1) {
            sp2 += __shfl_xor_sync(0xFFFFFFFFu, sp2, o);
            spa += __shfl_xor_sync(0xFFFFFFFFu, spa, o);
            sa2 += __shfl_xor_sync(0xFFFFFFFFu, sa2, o);
        }
        if ((tid & 31) == 0) {
            red[0][tid >> 5] = sp2; red[1][tid >> 5] = spa; red[2][tid >> 5] = sa2;
        }
        __syncthreads();
        if (tid == 0) {
            float t0 = 0.f, t1 = 0.f, t2 = 0.f;
            #pragma unroll
            for (int w = 0; w < 8; w++) { t0 += red[0][w]; t1 += red[1][w]; t2 += red[2][w]; }
            g_p2[c] = t0; g_pa[c] = t1; g_an[c] = sqrtf(t2);
        }
    }
}

// ---------------------------------------------------------------------------
// Epilogue math: 1 MUFU (rsqrt), no division, no log.
// ---------------------------------------------------------------------------
__device__ __forceinline__ float hyp_logit(float px, float xa, float x2,
                                           float p2, float pa, float an) {
    const float A   = 1.0f - 2.0f * px + x2;
    const float Bc  = 1.0f - p2;
    const float den = fmaxf(fmaf(x2, p2, fmaf(-2.0f, px, 1.0f)), EPSV);
    const float w   = fmaxf(fmaf(A * A, p2, fmaf(Bc * Bc, x2, -2.0f * A * Bc * px)), 0.0f);
    const float u   = fmaf(Bc, xa, -A * pa);
    const float N   = 2.0f * u * den;
    const float D   = fmaf(den, den, w) * an;
    const float z   = N * rsqrtf(fmaf(N, N, D * D));
    const float t   = z * z;
    float s = 1.0f / 25.0f;
    s = fmaf(s, t, 1.0f / 23.0f); s = fmaf(s, t, 1.0f / 21.0f);
    s = fmaf(s, t, 1.0f / 19.0f); s = fmaf(s, t, 1.0f / 17.0f);
    s = fmaf(s, t, 1.0f / 15.0f); s = fmaf(s, t, 1.0f / 13.0f);
    s = fmaf(s, t, 1.0f / 11.0f); s = fmaf(s, t, 1.0f / 9.0f);
    s = fmaf(s, t, 1.0f / 7.0f);  s = fmaf(s, t, 1.0f / 5.0f);
    s = fmaf(s, t, 1.0f / 3.0f);  s = fmaf(s, t, 1.0f);
    return -z * s;
}

// ---------------------------------------------------------------------------
// Main kernel: dual pure-bf16 GEMM via mma.sync + fused epilogue
//   CTA 128(batch) x 64(class), 256 threads (8 warps: 2 m x 4 n),
//   warp tile 64x16, BK=64, 3-stage cp.async pipeline, 2 CTAs/SM.
//   Stage layout: x tile rows [0,128), p rows [128,192), a rows [192,256).
// ---------------------------------------------------------------------------
#define BM 128
#define BN 64
#define BK 64
#define NKIT (DDIM / BK)          // 16
#define NSTG 3
#define ROWB 144                  // 128 data + 16 pad (conflict-free ldmatrix)
#define STAGEB (256 * ROWB)       // 36864
#define SMEM_NEED (NSTG * STAGEB) // 110592

__global__ __launch_bounds__(256, 2) void mlr_mma_kernel(float* __restrict__ out) {
    extern __shared__ char sm[];
    const uint32_t sb = smem_u32(sm);
    const int tid  = threadIdx.x;
    const int wid  = tid >> 5;
    const int lane = tid & 31;
    const int wn = wid & 3;        // warp col (class):  4 x 16
    const int wm = wid >> 2;       // warp row (batch):  2 x 64
    const int cb = blockIdx.x * BN;
    const int rb = blockIdx.y * BM;

    // loader mapping: 256 rows x 8 chunks(16B) = 2048 chunks, 8 per thread.
    // iteration t covers rows [t*32, t*32+32): t<4 -> x, t in {4,5} -> p, else a.
    const int lr = tid >> 3;       // 0..31 (row within 32-row group)
    const int lch = tid & 7;       // 16B chunk in row
    const __nv_bfloat16* lsrc[8];
    #pragma unroll
    for (int t = 0; t < 8; t++) {
        const int R = t * 32 + lr;
        const __nv_bfloat16* base =
            (t < 4) ? (g_xhi + (size_t)(rb + R) * DDIM)
                    : (t < 6) ? (g_phi + (size_t)(cb + R - 128) * DDIM)
                              : (g_ahi + (size_t)(cb + R - 192) * DDIM);
        lsrc[t] = base + lch * 8;
    }
    const uint32_t ldst = sb + lr * ROWB + lch * 16;

    // ldmatrix lane mappings
    const int a_r = lane & 15;
    const int a_c = lane >> 4;
    const int b_r = (lane & 7) | ((lane & 16) >> 1);
    const int b_h = (lane >> 3) & 1;
    const uint32_t smA = (wm * 64 + a_r) * ROWB + a_c * 16;
    const uint32_t smP = (128 + wn * 16 + b_r) * ROWB + b_h * 16;
    const uint32_t smQ = (192 + wn * 16 + b_r) * ROWB + b_h * 16;

    float cP[4][2][4];
    float cA[4][2][4];
    #pragma unroll
    for (int mt = 0; mt < 4; mt++)
        #pragma unroll
        for (int nt = 0; nt < 2; nt++)
            #pragma unroll
            for (int i = 0; i < 4; i++) { cP[mt][nt][i] = 0.f; cA[mt][nt][i] = 0.f; }

    // prologue: stages 0..1
    #pragma unroll
    for (int s = 0; s < NSTG - 1; s++) {
        #pragma unroll
        for (int t = 0; t < 8; t++)
            CP_ASYNC16(ldst + s * STAGEB + t * 32 * ROWB, lsrc[t] + (size_t)s * BK);
        asm volatile("cp.async.commit_group;" ::: "memory");
    }

    for (int k = 0; k < NKIT; k++) {
        asm volatile("cp.async.wait_group %0;" :: "n"(NSTG - 2) : "memory");
        __syncthreads();

        if (k + NSTG - 1 < NKIT) {
            const int s = (k + NSTG - 1) % NSTG;
            const size_t ko = (size_t)(k + NSTG - 1) * BK;
            #pragma unroll
            for (int t = 0; t < 8; t++)
                CP_ASYNC16(ldst + s * STAGEB + t * 32 * ROWB, lsrc[t] + ko);
        }
        asm volatile("cp.async.commit_group;" ::: "memory");

        const uint32_t st = sb + (k % NSTG) * STAGEB;
        #pragma unroll
        for (int ks = 0; ks < 4; ks++) {
            const uint32_t kofs = ks * 32;   // 16 bf16 = 32 bytes along K
            uint32_t bp[4], ba[4];
            LDSM4(bp, st + smP + kofs);
            LDSM4(ba, st + smQ + kofs);
            uint32_t xh[4][4];
            #pragma unroll
            for (int mt = 0; mt < 4; mt++)
                LDSM4(xh[mt], st + smA + mt * 16 * ROWB + kofs);
            #pragma unroll
            for (int mt = 0; mt < 4; mt++) {
                #pragma unroll
                for (int nt = 0; nt < 2; nt++) {
                    MMA16816(cP[mt][nt], xh[mt], bp[nt * 2], bp[nt * 2 + 1]);
                    MMA16816(cA[mt][nt], xh[mt], ba[nt * 2], ba[nt * 2 + 1]);
                }
            }
        }
        __syncthreads();
    }

    // epilogue
    const int g  = lane >> 2;
    const int tg = lane & 3;
    #pragma unroll
    for (int mt = 0; mt < 4; mt++) {
        #pragma unroll
        for (int h = 0; h < 2; h++) {
            const int row = rb + wm * 64 + mt * 16 + h * 8 + g;
            const float x2 = g_x2[row];
            float* orow = out + (size_t)row * CDIM + cb + wn * 16;
            #pragma unroll
            for (int nt = 0; nt < 2; nt++) {
                const int col = cb + wn * 16 + nt * 8 + tg * 2;
                float2 r;
                r.x = hyp_logit(cP[mt][nt][2 * h],     cA[mt][nt][2 * h],     x2,
                                g_p2[col],     g_pa[col],     g_an[col]);
                r.y = hyp_logit(cP[mt][nt][2 * h + 1], cA[mt][nt][2 * h + 1], x2,
                                g_p2[col + 1], g_pa[col + 1], g_an[col + 1]);
                *(float2*)(orow + nt * 8 + tg * 2) = r;
            }
        }
    }
}

// ---------------------------------------------------------------------------
extern "C" void kernel_launch(void* const* d_in, const int* in_sizes, int n_in,
                              void* d_out, int out_size) {
    const float* x = (const float*)d_in[0];
    const float* a = (const float*)d_in[1];
    const float* p = (const float*)d_in[2];
    float* out = (float*)d_out;

    cudaFuncSetAttribute(mlr_mma_kernel,
                         cudaFuncAttributeMaxDynamicSharedMemorySize, SMEM_NEED);

    prep_kernel<<<BDIM + CDIM, 256>>>(x, a, p);
    dim3 grid(CDIM / BN, BDIM / BM);
    mlr_mma_kernel<<<grid, 256, SMEM_NEED>>>(out);
}

// round 8
// speedup vs baseline: 1.0627x; 1.0318x over previous
#include <cuda_runtime.h>
#include <cuda_bf16.h>
#include <math.h>
#include <cstdint>

// Fixed shapes for HyperbolicMLR_33045478375870
#define BDIM 4096
#define DDIM 1024
#define CDIM 4096
#define EPSV 1e-15f
#define MAXN 0.99999f   // (1 - 1e-5)/sqrt(c), c = 1

// ---------------------------------------------------------------------------
// Device scratch (no allocations allowed)
// ---------------------------------------------------------------------------
__device__ __nv_bfloat16 g_xhi[(size_t)BDIM * DDIM];
__device__ __nv_bfloat16 g_phi[(size_t)CDIM * DDIM];
__device__ __nv_bfloat16 g_ahi[(size_t)CDIM * DDIM];
__device__ float g_x2[BDIM];
__device__ float g_p2[CDIM];
__device__ float g_pa[CDIM];
__device__ float g_an[CDIM];

// ---------------------------------------------------------------------------
__device__ __forceinline__ uint32_t smem_u32(const void* p) {
    uint32_t a;
    asm("{ .reg .u64 t; cvta.to.shared.u64 t, %1; cvt.u32.u64 %0, t; }"
        : "=r"(a) : "l"(p));
    return a;
}

#define LDSM4(r, addr) \
    asm volatile("ldmatrix.sync.aligned.m8n8.x4.shared.b16 {%0,%1,%2,%3}, [%4];" \
                 : "=r"((r)[0]), "=r"((r)[1]), "=r"((r)[2]), "=r"((r)[3]) \
                 : "r"(addr))

#define MMA16816(c, a, b0, b1) \
    asm volatile("mma.sync.aligned.m16n8k16.row.col.f32.bf16.bf16.f32 " \
                 "{%0,%1,%2,%3},{%4,%5,%6,%7},{%8,%9},{%0,%1,%2,%3};" \
                 : "+f"((c)[0]), "+f"((c)[1]), "+f"((c)[2]), "+f"((c)[3]) \
                 : "r"((a)[0]), "r"((a)[1]), "r"((a)[2]), "r"((a)[3]), \
                   "r"(b0), "r"(b1))

#define CP_ASYNC16(dst, src) \
    asm volatile("cp.async.cg.shared.global [%0], [%1], 16;" \
                 :: "r"(dst), "l"(__cvta_generic_to_global(src)))

// ---------------------------------------------------------------------------
// Merged prep kernel (unchanged from R6/R7)
// ---------------------------------------------------------------------------
__global__ __launch_bounds__(256) void prep_kernel(const float* __restrict__ x,
                                                   const float* __restrict__ a,
                                                   const float* __restrict__ p) {
    const int blk = blockIdx.x;
    const int tid = threadIdx.x;
    __shared__ float red[3][8];

    if (blk < BDIM) {
        const int b = blk;
        const float4 v = ((const float4*)(x + (size_t)b * DDIM))[tid];
        float s = v.x * v.x + v.y * v.y + v.z * v.z + v.w * v.w;
        #pragma unroll
        for (int o = 16; o > 0; o >>= 1) s += __shfl_xor_sync(0xFFFFFFFFu, s, o);
        if ((tid & 31) == 0) red[0][tid >> 5] = s;
        __syncthreads();
        __shared__ float sh_scale;
        if (tid == 0) {
            float tot = 0.f;
            #pragma unroll
            for (int w = 0; w < 8; w++) tot += red[0][w];
            float xn = fmaxf(sqrtf(tot), EPSV);
            float scale = (xn > MAXN) ? (MAXN / xn) : 1.0f;
            sh_scale = scale;
            g_x2[b] = tot * scale * scale;
        }
        __syncthreads();
        const float sc = sh_scale;
        __nv_bfloat162 o0 = {__float2bfloat16(v.x * sc), __float2bfloat16(v.y * sc)};
        __nv_bfloat162 o1 = {__float2bfloat16(v.z * sc), __float2bfloat16(v.w * sc)};
        ((__nv_bfloat162*)(g_xhi + (size_t)b * DDIM))[tid * 2]     = o0;
        ((__nv_bfloat162*)(g_xhi + (size_t)b * DDIM))[tid * 2 + 1] = o1;
    } else {
        const int c = blk - BDIM;
        const float4 pv = ((const float4*)(p + (size_t)c * DDIM))[tid];
        const float4 av = ((const float4*)(a + (size_t)c * DDIM))[tid];
        float sp2 = pv.x * pv.x + pv.y * pv.y + pv.z * pv.z + pv.w * pv.w;
        float spa = pv.x * av.x + pv.y * av.y + pv.z * av.z + pv.w * av.w;
        float sa2 = av.x * av.x + av.y * av.y + av.z * av.z + av.w * av.w;
        __nv_bfloat162 p0 = {__float2bfloat16(pv.x), __float2bfloat16(pv.y)};
        __nv_bfloat162 p1 = {__float2bfloat16(pv.z), __float2bfloat16(pv.w)};
        __nv_bfloat162 a0 = {__float2bfloat16(av.x), __float2bfloat16(av.y)};
        __nv_bfloat162 a1 = {__float2bfloat16(av.z), __float2bfloat16(av.w)};
        ((__nv_bfloat162*)(g_phi + (size_t)c * DDIM))[tid * 2]     = p0;
        ((__nv_bfloat162*)(g_phi + (size_t)c * DDIM))[tid * 2 + 1] = p1;
        ((__nv_bfloat162*)(g_ahi + (size_t)c * DDIM))[tid * 2]     = a0;
        ((__nv_bfloat162*)(g_ahi + (size_t)c * DDIM))[tid * 2 + 1] = a1;
        #pragma unroll
        for (int o = 16; o > 0; o >>= 1) {
            sp2 += __shfl_xor_sync(0xFFFFFFFFu, sp2, o);
            spa += __shfl_xor_sync(0xFFFFFFFFu, spa, o);
            sa2 += __shfl_xor_sync(0xFFFFFFFFu, sa2, o);
        }
        if ((tid & 31) == 0) {
            red[0][tid >> 5] = sp2; red[1][tid >> 5] = spa; red[2][tid >> 5] = sa2;
        }
        __syncthreads();
        if (tid == 0) {
            float t0 = 0.f, t1 = 0.f, t2 = 0.f;
            #pragma unroll
            for (int w = 0; w < 8; w++) { t0 += red[0][w]; t1 += red[1][w]; t2 += red[2][w]; }
            g_p2[c] = t0; g_pa[c] = t1; g_an[c] = sqrtf(t2);
        }
    }
}

// ---------------------------------------------------------------------------
// Epilogue math: 1 MUFU (rsqrt), no division, no log.
// ---------------------------------------------------------------------------
__device__ __forceinline__ float hyp_logit(float px, float xa, float x2,
                                           float p2, float pa, float an) {
    const float A   = 1.0f - 2.0f * px + x2;
    const float Bc  = 1.0f - p2;
    const float den = fmaxf(fmaf(x2, p2, fmaf(-2.0f, px, 1.0f)), EPSV);
    const float w   = fmaxf(fmaf(A * A, p2, fmaf(Bc * Bc, x2, -2.0f * A * Bc * px)), 0.0f);
    const float u   = fmaf(Bc, xa, -A * pa);
    const float N   = 2.0f * u * den;
    const float D   = fmaf(den, den, w) * an;
    const float z   = N * rsqrtf(fmaf(N, N, D * D));
    const float t   = z * z;
    float s = 1.0f / 25.0f;
    s = fmaf(s, t, 1.0f / 23.0f); s = fmaf(s, t, 1.0f / 21.0f);
    s = fmaf(s, t, 1.0f / 19.0f); s = fmaf(s, t, 1.0f / 17.0f);
    s = fmaf(s, t, 1.0f / 15.0f); s = fmaf(s, t, 1.0f / 13.0f);
    s = fmaf(s, t, 1.0f / 11.0f); s = fmaf(s, t, 1.0f / 9.0f);
    s = fmaf(s, t, 1.0f / 7.0f);  s = fmaf(s, t, 1.0f / 5.0f);
    s = fmaf(s, t, 1.0f / 3.0f);  s = fmaf(s, t, 1.0f);
    return -z * s;
}

// ---------------------------------------------------------------------------
// Main kernel: dual pure-bf16 GEMM via mma.sync + fused epilogue
//   CTA 128(batch) x 64(class), 256 threads (8 warps: 2 m x 4 n),
//   warp tile 64x16, BK=64, 3-stage cp.async pipeline, 2 CTAs/SM.
//   ks-software-pipelined B fragments; single __syncthreads per k-iter.
// ---------------------------------------------------------------------------
#define BM 128
#define BN 64
#define BK 64
#define NKIT (DDIM / BK)          // 16
#define NSTG 3
#define ROWB 144                  // 128 data + 16 pad (conflict-free ldmatrix)
#define STAGEB (256 * ROWB)       // 36864
#define SMEM_NEED (NSTG * STAGEB) // 110592

__global__ __launch_bounds__(256, 2) void mlr_mma_kernel(float* __restrict__ out) {
    extern __shared__ char sm[];
    const uint32_t sb = smem_u32(sm);
    const int tid  = threadIdx.x;
    const int wid  = tid >> 5;
    const int lane = tid & 31;
    const int wn = wid & 3;        // warp col (class):  4 x 16
    const int wm = wid >> 2;       // warp row (batch):  2 x 64
    const int cb = blockIdx.x * BN;
    const int rb = blockIdx.y * BM;

    // loader mapping: 3 base pointers + immediate offsets (saves regs vs array)
    const int lr = tid >> 3;       // 0..31
    const int lch = tid & 7;       // 16B chunk in row
    const __nv_bfloat16* xb = g_xhi + (size_t)(rb + lr) * DDIM + lch * 8;
    const __nv_bfloat16* pb = g_phi + (size_t)(cb + lr) * DDIM + lch * 8;
    const __nv_bfloat16* ab = g_ahi + (size_t)(cb + lr) * DDIM + lch * 8;
    const uint32_t ldst = sb + lr * ROWB + lch * 16;

    // cp.async issue for one stage: x rows [0,128), p rows [128,192), a [192,256)
    #define ISSUE_STAGE(slot, ko)                                              \
        do {                                                                   \
            const uint32_t _d = ldst + (slot) * STAGEB;                        \
            CP_ASYNC16(_d,                   xb + (ko));                       \
            CP_ASYNC16(_d + 32 * ROWB,       xb + (ko) + (size_t)32 * DDIM);   \
            CP_ASYNC16(_d + 64 * ROWB,       xb + (ko) + (size_t)64 * DDIM);   \
            CP_ASYNC16(_d + 96 * ROWB,       xb + (ko) + (size_t)96 * DDIM);   \
            CP_ASYNC16(_d + 128 * ROWB,      pb + (ko));                       \
            CP_ASYNC16(_d + 160 * ROWB,      pb + (ko) + (size_t)32 * DDIM);   \
            CP_ASYNC16(_d + 192 * ROWB,      ab + (ko));                       \
            CP_ASYNC16(_d + 224 * ROWB,      ab + (ko) + (size_t)32 * DDIM);   \
        } while (0)

    // ldmatrix lane mappings
    const int a_r = lane & 15;
    const int a_c = lane >> 4;
    const int b_r = (lane & 7) | ((lane & 16) >> 1);
    const int b_h = (lane >> 3) & 1;
    const uint32_t smA = (wm * 64 + a_r) * ROWB + a_c * 16;
    const uint32_t smP = (128 + wn * 16 + b_r) * ROWB + b_h * 16;
    const uint32_t smQ = (192 + wn * 16 + b_r) * ROWB + b_h * 16;

    float cP[4][2][4];
    float cA[4][2][4];
    #pragma unroll
    for (int mt = 0; mt < 4; mt++)
        #pragma unroll
        for (int nt = 0; nt < 2; nt++)
            #pragma unroll
            for (int i = 0; i < 4; i++) { cP[mt][nt][i] = 0.f; cA[mt][nt][i] = 0.f; }

    // prologue: stages 0..1
    ISSUE_STAGE(0, 0);
    asm volatile("cp.async.commit_group;" ::: "memory");
    ISSUE_STAGE(1, BK);
    asm volatile("cp.async.commit_group;" ::: "memory");

    for (int k = 0; k < NKIT; k++) {
        asm volatile("cp.async.wait_group %0;" :: "n"(NSTG - 2) : "memory");
        __syncthreads();

        const uint32_t st = sb + (k % NSTG) * STAGEB;
        const int nslot = (k + NSTG - 1) % NSTG;
        const size_t nko = (size_t)(k + NSTG - 1) * BK;
        const bool do_issue = (k + NSTG - 1 < NKIT);

        // B-fragment double buffer, pipelined across the 4 ks sub-iters
        uint32_t bp[2][4], ba[2][4];
        LDSM4(bp[0], st + smP);
        LDSM4(ba[0], st + smQ);

        #pragma unroll
        for (int ks = 0; ks < 4; ks++) {
            const int cur = ks & 1;
            const uint32_t kofs = ks * 32;
            uint32_t xh[4][4];
            #pragma unroll
            for (int mt = 0; mt < 4; mt++)
                LDSM4(xh[mt], st + smA + mt * 16 * ROWB + kofs);
            if (ks < 3) {
                LDSM4(bp[cur ^ 1], st + smP + kofs + 32);
                LDSM4(ba[cur ^ 1], st + smQ + kofs + 32);
            }
            if (ks == 1) {   // spread LSU: issue next-stage loads after first MMAs
                if (do_issue) ISSUE_STAGE(nslot, nko);
                asm volatile("cp.async.commit_group;" ::: "memory");
            }
            #pragma unroll
            for (int mt = 0; mt < 4; mt++) {
                #pragma unroll
                for (int nt = 0; nt < 2; nt++) {
                    MMA16816(cP[mt][nt], xh[mt], bp[cur][nt * 2], bp[cur][nt * 2 + 1]);
                    MMA16816(cA[mt][nt], xh[mt], ba[cur][nt * 2], ba[cur][nt * 2 + 1]);
                }
            }
        }
    }

    // epilogue
    const int g  = lane >> 2;
    const int tg = lane & 3;
    #pragma unroll
    for (int mt = 0; mt < 4; mt++) {
        #pragma unroll
        for (int h = 0; h < 2; h++) {
            const int row = rb + wm * 64 + mt * 16 + h * 8 + g;
            const float x2 = g_x2[row];
            float* orow = out + (size_t)row * CDIM + cb + wn * 16;
            #pragma unroll
            for (int nt = 0; nt < 2; nt++) {
                const int col = cb + wn * 16 + nt * 8 + tg * 2;
                float2 r;
                r.x = hyp_logit(cP[mt][nt][2 * h],     cA[mt][nt][2 * h],     x2,
                                g_p2[col],     g_pa[col],     g_an[col]);
                r.y = hyp_logit(cP[mt][nt][2 * h + 1], cA[mt][nt][2 * h + 1], x2,
                                g_p2[col + 1], g_pa[col + 1], g_an[col + 1]);
                *(float2*)(orow + nt * 8 + tg * 2) = r;
            }
        }
    }
    #undef ISSUE_STAGE
}

// ---------------------------------------------------------------------------
extern "C" void kernel_launch(void* const* d_in, const int* in_sizes, int n_in,
                              void* d_out, int out_size) {
    const float* x = (const float*)d_in[0];
    const float* a = (const float*)d_in[1];
    const float* p = (const float*)d_in[2];
    float* out = (float*)d_out;

    cudaFuncSetAttribute(mlr_mma_kernel,
                         cudaFuncAttributeMaxDynamicSharedMemorySize, SMEM_NEED);

    prep_kernel<<<BDIM + CDIM, 256>>>(x, a, p);
    dim3 grid(CDIM / BN, BDIM / BM);
    mlr_mma_kernel<<<grid, 256, SMEM_NEED>>>(out);
}

// round 9
// speedup vs baseline: 1.0894x; 1.0251x over previous
#include <cuda_runtime.h>
#include <cuda_bf16.h>
#include <math.h>
#include <cstdint>

// Fixed shapes for HyperbolicMLR_33045478375870
#define BDIM 4096
#define DDIM 1024
#define CDIM 4096
#define EPSV 1e-15f
#define MAXN 0.99999f   // (1 - 1e-5)/sqrt(c), c = 1

// ---------------------------------------------------------------------------
// Device scratch (no allocations allowed)
// ---------------------------------------------------------------------------
__device__ __nv_bfloat16 g_xhi[(size_t)BDIM * DDIM];
__device__ __nv_bfloat16 g_phi[(size_t)CDIM * DDIM];
__device__ __nv_bfloat16 g_ahi[(size_t)CDIM * DDIM];
__device__ float g_x2[BDIM];
__device__ float g_p2[CDIM];
__device__ float g_pa[CDIM];
__device__ float g_an[CDIM];

// ---------------------------------------------------------------------------
__device__ __forceinline__ uint32_t smem_u32(const void* p) {
    uint32_t a;
    asm("{ .reg .u64 t; cvta.to.shared.u64 t, %1; cvt.u32.u64 %0, t; }"
        : "=r"(a) : "l"(p));
    return a;
}

#define LDSM4(r, addr) \
    asm volatile("ldmatrix.sync.aligned.m8n8.x4.shared.b16 {%0,%1,%2,%3}, [%4];" \
                 : "=r"((r)[0]), "=r"((r)[1]), "=r"((r)[2]), "=r"((r)[3]) \
                 : "r"(addr))

#define MMA16816(c, a, b0, b1) \
    asm volatile("mma.sync.aligned.m16n8k16.row.col.f32.bf16.bf16.f32 " \
                 "{%0,%1,%2,%3},{%4,%5,%6,%7},{%8,%9},{%0,%1,%2,%3};" \
                 : "+f"((c)[0]), "+f"((c)[1]), "+f"((c)[2]), "+f"((c)[3]) \
                 : "r"((a)[0]), "r"((a)[1]), "r"((a)[2]), "r"((a)[3]), \
                   "r"(b0), "r"(b1))

#define CP_ASYNC16(dst, src) \
    asm volatile("cp.async.cg.shared.global [%0], [%1], 16;" \
                 :: "r"(dst), "l"(__cvta_generic_to_global(src)))

// ---------------------------------------------------------------------------
// Merged prep kernel (unchanged)
// ---------------------------------------------------------------------------
__global__ __launch_bounds__(256) void prep_kernel(const float* __restrict__ x,
                                                   const float* __restrict__ a,
                                                   const float* __restrict__ p) {
    const int blk = blockIdx.x;
    const int tid = threadIdx.x;
    __shared__ float red[3][8];

    if (blk < BDIM) {
        const int b = blk;
        const float4 v = ((const float4*)(x + (size_t)b * DDIM))[tid];
        float s = v.x * v.x + v.y * v.y + v.z * v.z + v.w * v.w;
        #pragma unroll
        for (int o = 16; o > 0; o >>= 1) s += __shfl_xor_sync(0xFFFFFFFFu, s, o);
        if ((tid & 31) == 0) red[0][tid >> 5] = s;
        __syncthreads();
        __shared__ float sh_scale;
        if (tid == 0) {
            float tot = 0.f;
            #pragma unroll
            for (int w = 0; w < 8; w++) tot += red[0][w];
            float xn = fmaxf(sqrtf(tot), EPSV);
            float scale = (xn > MAXN) ? (MAXN / xn) : 1.0f;
            sh_scale = scale;
            g_x2[b] = tot * scale * scale;
        }
        __syncthreads();
        const float sc = sh_scale;
        __nv_bfloat162 o0 = {__float2bfloat16(v.x * sc), __float2bfloat16(v.y * sc)};
        __nv_bfloat162 o1 = {__float2bfloat16(v.z * sc), __float2bfloat16(v.w * sc)};
        ((__nv_bfloat162*)(g_xhi + (size_t)b * DDIM))[tid * 2]     = o0;
        ((__nv_bfloat162*)(g_xhi + (size_t)b * DDIM))[tid * 2 + 1] = o1;
    } else {
        const int c = blk - BDIM;
        const float4 pv = ((const float4*)(p + (size_t)c * DDIM))[tid];
        const float4 av = ((const float4*)(a + (size_t)c * DDIM))[tid];
        float sp2 = pv.x * pv.x + pv.y * pv.y + pv.z * pv.z + pv.w * pv.w;
        float spa = pv.x * av.x + pv.y * av.y + pv.z * av.z + pv.w * av.w;
        float sa2 = av.x * av.x + av.y * av.y + av.z * av.z + av.w * av.w;
        __nv_bfloat162 p0 = {__float2bfloat16(pv.x), __float2bfloat16(pv.y)};
        __nv_bfloat162 p1 = {__float2bfloat16(pv.z), __float2bfloat16(pv.w)};
        __nv_bfloat162 a0 = {__float2bfloat16(av.x), __float2bfloat16(av.y)};
        __nv_bfloat162 a1 = {__float2bfloat16(av.z), __float2bfloat16(av.w)};
        ((__nv_bfloat162*)(g_phi + (size_t)c * DDIM))[tid * 2]     = p0;
        ((__nv_bfloat162*)(g_phi + (size_t)c * DDIM))[tid * 2 + 1] = p1;
        ((__nv_bfloat162*)(g_ahi + (size_t)c * DDIM))[tid * 2]     = a0;
        ((__nv_bfloat162*)(g_ahi + (size_t)c * DDIM))[tid * 2 + 1] = a1;
        #pragma unroll
        for (int o = 16; o > 0; o >>= 1) {
            sp2 += __shfl_xor_sync(0xFFFFFFFFu, sp2, o);
            spa += __shfl_xor_sync(0xFFFFFFFFu, spa, o);
            sa2 += __shfl_xor_sync(0xFFFFFFFFu, sa2, o);
        }
        if ((tid & 31) == 0) {
            red[0][tid >> 5] = sp2; red[1][tid >> 5] = spa; red[2][tid >> 5] = sa2;
        }
        __syncthreads();
        if (tid == 0) {
            float t0 = 0.f, t1 = 0.f, t2 = 0.f;
            #pragma unroll
            for (int w = 0; w < 8; w++) { t0 += red[0][w]; t1 += red[1][w]; t2 += red[2][w]; }
            g_p2[c] = t0; g_pa[c] = t1; g_an[c] = sqrtf(t2);
        }
    }
}

// ---------------------------------------------------------------------------
// Epilogue math: 1 MUFU (rsqrt), no division, no log.
// ---------------------------------------------------------------------------
__device__ __forceinline__ float hyp_logit(float px, float xa, float x2,
                                           float p2, float pa, float an) {
    const float A   = 1.0f - 2.0f * px + x2;
    const float Bc  = 1.0f - p2;
    const float den = fmaxf(fmaf(x2, p2, fmaf(-2.0f, px, 1.0f)), EPSV);
    const float w   = fmaxf(fmaf(A * A, p2, fmaf(Bc * Bc, x2, -2.0f * A * Bc * px)), 0.0f);
    const float u   = fmaf(Bc, xa, -A * pa);
    const float N   = 2.0f * u * den;
    const float D   = fmaf(den, den, w) * an;
    const float z   = N * rsqrtf(fmaf(N, N, D * D));
    const float t   = z * z;
    float s = 1.0f / 25.0f;
    s = fmaf(s, t, 1.0f / 23.0f); s = fmaf(s, t, 1.0f / 21.0f);
    s = fmaf(s, t, 1.0f / 19.0f); s = fmaf(s, t, 1.0f / 17.0f);
    s = fmaf(s, t, 1.0f / 15.0f); s = fmaf(s, t, 1.0f / 13.0f);
    s = fmaf(s, t, 1.0f / 11.0f); s = fmaf(s, t, 1.0f / 9.0f);
    s = fmaf(s, t, 1.0f / 7.0f);  s = fmaf(s, t, 1.0f / 5.0f);
    s = fmaf(s, t, 1.0f / 3.0f);  s = fmaf(s, t, 1.0f);
    return -z * s;
}

// ---------------------------------------------------------------------------
// Main kernel: dual pure-bf16 GEMM via mma.sync + fused epilogue
//   CTA 128(batch) x 64(class), 256 threads (8 warps: 2 m x 4 n),
//   warp tile 64x16, BK=64, 3-stage cp.async pipeline, 2 CTAs/SM.
//   NEW: per-warp ks phase rotation (rot = 2*wm) anti-phases the two
//   same-SMSP warps so LDSM (L1) and MMA (tensor) bursts overlap.
// ---------------------------------------------------------------------------
#define BM 128
#define BN 64
#define BK 64
#define NKIT (DDIM / BK)          // 16
#define NSTG 3
#define ROWB 144                  // 128 data + 16 pad (conflict-free ldmatrix)
#define STAGEB (256 * ROWB)       // 36864
#define SMEM_NEED (NSTG * STAGEB) // 110592

__global__ __launch_bounds__(256, 2) void mlr_mma_kernel(float* __restrict__ out) {
    extern __shared__ char sm[];
    const uint32_t sb = smem_u32(sm);
    const int tid  = threadIdx.x;
    const int wid  = tid >> 5;
    const int lane = tid & 31;
    const int wn = wid & 3;        // warp col (class):  4 x 16
    const int wm = wid >> 2;       // warp row (batch):  2 x 64
    const int cb = blockIdx.x * BN;
    const int rb = blockIdx.y * BM;
    const int rot = wm << 1;       // ks phase rotation: 0 or 2

    // loader mapping: 3 base pointers + immediate offsets
    const int lr = tid >> 3;       // 0..31
    const int lch = tid & 7;       // 16B chunk in row
    const __nv_bfloat16* xb = g_xhi + (size_t)(rb + lr) * DDIM + lch * 8;
    const __nv_bfloat16* pb = g_phi + (size_t)(cb + lr) * DDIM + lch * 8;
    const __nv_bfloat16* ab = g_ahi + (size_t)(cb + lr) * DDIM + lch * 8;
    const uint32_t ldst = sb + lr * ROWB + lch * 16;

    #define ISSUE_STAGE(slot, ko)                                              \
        do {                                                                   \
            const uint32_t _d = ldst + (slot) * STAGEB;                        \
            CP_ASYNC16(_d,                   xb + (ko));                       \
            CP_ASYNC16(_d + 32 * ROWB,       xb + (ko) + (size_t)32 * DDIM);   \
            CP_ASYNC16(_d + 64 * ROWB,       xb + (ko) + (size_t)64 * DDIM);   \
            CP_ASYNC16(_d + 96 * ROWB,       xb + (ko) + (size_t)96 * DDIM);   \
            CP_ASYNC16(_d + 128 * ROWB,      pb + (ko));                       \
            CP_ASYNC16(_d + 160 * ROWB,      pb + (ko) + (size_t)32 * DDIM);   \
            CP_ASYNC16(_d + 192 * ROWB,      ab + (ko));                       \
            CP_ASYNC16(_d + 224 * ROWB,      ab + (ko) + (size_t)32 * DDIM);   \
        } while (0)

    // ldmatrix lane mappings
    const int a_r = lane & 15;
    const int a_c = lane >> 4;
    const int b_r = (lane & 7) | ((lane & 16) >> 1);
    const int b_h = (lane >> 3) & 1;
    const uint32_t smA = (wm * 64 + a_r) * ROWB + a_c * 16;
    const uint32_t smP = (128 + wn * 16 + b_r) * ROWB + b_h * 16;
    const uint32_t smQ = (192 + wn * 16 + b_r) * ROWB + b_h * 16;

    float cP[4][2][4];
    float cA[4][2][4];
    #pragma unroll
    for (int mt = 0; mt < 4; mt++)
        #pragma unroll
        for (int nt = 0; nt < 2; nt++)
            #pragma unroll
            for (int i = 0; i < 4; i++) { cP[mt][nt][i] = 0.f; cA[mt][nt][i] = 0.f; }

    // prologue: stages 0..1
    ISSUE_STAGE(0, 0);
    asm volatile("cp.async.commit_group;" ::: "memory");
    ISSUE_STAGE(1, BK);
    asm volatile("cp.async.commit_group;" ::: "memory");

    for (int k = 0; k < NKIT; k++) {
        asm volatile("cp.async.wait_group %0;" :: "n"(NSTG - 2) : "memory");
        __syncthreads();

        const uint32_t st = sb + (k % NSTG) * STAGEB;
        const int nslot = (k + NSTG - 1) % NSTG;
        const size_t nko = (size_t)(k + NSTG - 1) * BK;
        const bool do_issue = (k + NSTG - 1 < NKIT);

        // B-fragment double buffer over the warp's ROTATED ks order
        uint32_t bp[2][4], ba[2][4];
        const uint32_t kof0 = ((0 + rot) & 3) * 32;
        LDSM4(bp[0], st + smP + kof0);
        LDSM4(ba[0], st + smQ + kof0);

        #pragma unroll
        for (int ks = 0; ks < 4; ks++) {
            const int cur = ks & 1;
            const uint32_t kofs = ((ks + rot) & 3) * 32;
            uint32_t xh[4][4];
            #pragma unroll
            for (int mt = 0; mt < 4; mt++)
                LDSM4(xh[mt], st + smA + mt * 16 * ROWB + kofs);
            if (ks < 3) {
                const uint32_t knx = ((ks + 1 + rot) & 3) * 32;
                LDSM4(bp[cur ^ 1], st + smP + knx);
                LDSM4(ba[cur ^ 1], st + smQ + knx);
            }
            if (ks == 1) {   // spread LSU: issue next-stage loads mid-iteration
                if (do_issue) ISSUE_STAGE(nslot, nko);
                asm volatile("cp.async.commit_group;" ::: "memory");
            }
            #pragma unroll
            for (int mt = 0; mt < 4; mt++) {
                #pragma unroll
                for (int nt = 0; nt < 2; nt++) {
                    MMA16816(cP[mt][nt], xh[mt], bp[cur][nt * 2], bp[cur][nt * 2 + 1]);
                    MMA16816(cA[mt][nt], xh[mt], ba[cur][nt * 2], ba[cur][nt * 2 + 1]);
                }
            }
        }
    }

    // epilogue
    const int g  = lane >> 2;
    const int tg = lane & 3;
    #pragma unroll
    for (int mt = 0; mt < 4; mt++) {
        #pragma unroll
        for (int h = 0; h < 2; h++) {
            const int row = rb + wm * 64 + mt * 16 + h * 8 + g;
            const float x2 = g_x2[row];
            float* orow = out + (size_t)row * CDIM + cb + wn * 16;
            #pragma unroll
            for (int nt = 0; nt < 2; nt++) {
                const int col = cb + wn * 16 + nt * 8 + tg * 2;
                float2 r;
                r.x = hyp_logit(cP[mt][nt][2 * h],     cA[mt][nt][2 * h],     x2,
                                g_p2[col],     g_pa[col],     g_an[col]);
                r.y = hyp_logit(cP[mt][nt][2 * h + 1], cA[mt][nt][2 * h + 1], x2,
                                g_p2[col + 1], g_pa[col + 1], g_an[col + 1]);
                *(float2*)(orow + nt * 8 + tg * 2) = r;
            }
        }
    }
    #undef ISSUE_STAGE
}

// ---------------------------------------------------------------------------
extern "C" void kernel_launch(void* const* d_in, const int* in_sizes, int n_in,
                              void* d_out, int out_size) {
    const float* x = (const float*)d_in[0];
    const float* a = (const float*)d_in[1];
    const float* p = (const float*)d_in[2];
    float* out = (float*)d_out;

    cudaFuncSetAttribute(mlr_mma_kernel,
                         cudaFuncAttributeMaxDynamicSharedMemorySize, SMEM_NEED);

    prep_kernel<<<BDIM + CDIM, 256>>>(x, a, p);
    dim3 grid(CDIM / BN, BDIM / BM);
    mlr_mma_kernel<<<grid, 256, SMEM_NEED>>>(out);
}

// round 10
// speedup vs baseline: 1.1351x; 1.0420x over previous
#include <cuda_runtime.h>
#include <cuda_bf16.h>
#include <math.h>
#include <cstdint>

// Fixed shapes for HyperbolicMLR_33045478375870
#define BDIM 4096
#define DDIM 1024
#define CDIM 4096
#define EPSV 1e-15f
#define MAXN 0.99999f   // (1 - 1e-5)/sqrt(c), c = 1

// ---------------------------------------------------------------------------
// Device scratch (no allocations allowed)
// ---------------------------------------------------------------------------
__device__ __nv_bfloat16 g_xhi[(size_t)BDIM * DDIM];
__device__ __nv_bfloat16 g_phi[(size_t)CDIM * DDIM];
__device__ __nv_bfloat16 g_ahi[(size_t)CDIM * DDIM];
__device__ float g_x2[BDIM];
__device__ float g_p2[CDIM];
__device__ float g_pa[CDIM];
__device__ float g_an[CDIM];

// ---------------------------------------------------------------------------
__device__ __forceinline__ uint32_t smem_u32(const void* p) {
    uint32_t a;
    asm("{ .reg .u64 t; cvta.to.shared.u64 t, %1; cvt.u32.u64 %0, t; }"
        : "=r"(a) : "l"(p));
    return a;
}

#define LDSM4(r, addr) \
    asm volatile("ldmatrix.sync.aligned.m8n8.x4.shared.b16 {%0,%1,%2,%3}, [%4];" \
                 : "=r"((r)[0]), "=r"((r)[1]), "=r"((r)[2]), "=r"((r)[3]) \
                 : "r"(addr))

#define MMA16816(c, a, b0, b1) \
    asm volatile("mma.sync.aligned.m16n8k16.row.col.f32.bf16.bf16.f32 " \
                 "{%0,%1,%2,%3},{%4,%5,%6,%7},{%8,%9},{%0,%1,%2,%3};" \
                 : "+f"((c)[0]), "+f"((c)[1]), "+f"((c)[2]), "+f"((c)[3]) \
                 : "r"((a)[0]), "r"((a)[1]), "r"((a)[2]), "r"((a)[3]), \
                   "r"(b0), "r"(b1))

#define CP_ASYNC16(dst, src) \
    asm volatile("cp.async.cg.shared.global [%0], [%1], 16;" \
                 :: "r"(dst), "l"(__cvta_generic_to_global(src)))

#define MBARRIER_INIT(mbar, count) \
    asm volatile("mbarrier.init.shared.b64 [%0], %1;" \
                 :: "r"((uint32_t)(mbar)), "r"((uint32_t)(count)) : "memory")

#define MB_ARRIVE(mbar) \
    asm volatile("mbarrier.arrive.shared.b64 _, [%0];" \
                 :: "r"((uint32_t)(mbar)) : "memory")

#define CPX_ARRIVE(mbar) \
    asm volatile("cp.async.mbarrier.arrive.noinc.shared.b64 [%0];" \
                 :: "r"((uint32_t)(mbar)) : "memory")

#define MBARRIER_WAIT_PARITY(mbar, parity) do {                                   \
    uint32_t _mbar = (uint32_t)(mbar);                                            \
    uint32_t _par  = (uint32_t)(parity);                                          \
    uint32_t _done;                                                               \
    asm volatile(                                                                 \
        "{\n\t.reg .pred p;\n\t"                                                  \
        "mbarrier.try_wait.parity.acquire.cta.shared::cta.b64 p, [%1], %2;\n\t"   \
        "selp.b32 %0, 1, 0, p;\n\t}"                                              \
        : "=r"(_done) : "r"(_mbar), "r"(_par) : "memory");                        \
    if (!_done) {                                                                 \
        asm volatile(                                                             \
            "{\n\t.reg .pred P1;\n\t"                                             \
            "WAIT_LOOP_%=:\n\t"                                                   \
            "mbarrier.try_wait.parity.acquire.cta.shared::cta.b64 P1, [%0], %1, 0x989680;\n\t" \
            "@P1 bra.uni WAIT_DONE_%=;\n\t"                                       \
            "bra.uni WAIT_LOOP_%=;\n\t"                                           \
            "WAIT_DONE_%=:\n\t}"                                                  \
            :: "r"(_mbar), "r"(_par) : "memory");                                 \
    }                                                                             \
} while (0)

// ---------------------------------------------------------------------------
// Merged prep kernel (unchanged)
// ---------------------------------------------------------------------------
__global__ __launch_bounds__(256) void prep_kernel(const float* __restrict__ x,
                                                   const float* __restrict__ a,
                                                   const float* __restrict__ p) {
    const int blk = blockIdx.x;
    const int tid = threadIdx.x;
    __shared__ float red[3][8];

    if (blk < BDIM) {
        const int b = blk;
        const float4 v = ((const float4*)(x + (size_t)b * DDIM))[tid];
        float s = v.x * v.x + v.y * v.y + v.z * v.z + v.w * v.w;
        #pragma unroll
        for (int o = 16; o > 0; o >>= 1) s += __shfl_xor_sync(0xFFFFFFFFu, s, o);
        if ((tid & 31) == 0) red[0][tid >> 5] = s;
        __syncthreads();
        __shared__ float sh_scale;
        if (tid == 0) {
            float tot = 0.f;
            #pragma unroll
            for (int w = 0; w < 8; w++) tot += red[0][w];
            float xn = fmaxf(sqrtf(tot), EPSV);
            float scale = (xn > MAXN) ? (MAXN / xn) : 1.0f;
            sh_scale = scale;
            g_x2[b] = tot * scale * scale;
        }
        __syncthreads();
        const float sc = sh_scale;
        __nv_bfloat162 o0 = {__float2bfloat16(v.x * sc), __float2bfloat16(v.y * sc)};
        __nv_bfloat162 o1 = {__float2bfloat16(v.z * sc), __float2bfloat16(v.w * sc)};
        ((__nv_bfloat162*)(g_xhi + (size_t)b * DDIM))[tid * 2]     = o0;
        ((__nv_bfloat162*)(g_xhi + (size_t)b * DDIM))[tid * 2 + 1] = o1;
    } else {
        const int c = blk - BDIM;
        const float4 pv = ((const float4*)(p + (size_t)c * DDIM))[tid];
        const float4 av = ((const float4*)(a + (size_t)c * DDIM))[tid];
        float sp2 = pv.x * pv.x + pv.y * pv.y + pv.z * pv.z + pv.w * pv.w;
        float spa = pv.x * av.x + pv.y * av.y + pv.z * av.z + pv.w * av.w;
        float sa2 = av.x * av.x + av.y * av.y + av.z * av.z + av.w * av.w;
        __nv_bfloat162 p0 = {__float2bfloat16(pv.x), __float2bfloat16(pv.y)};
        __nv_bfloat162 p1 = {__float2bfloat16(pv.z), __float2bfloat16(pv.w)};
        __nv_bfloat162 a0 = {__float2bfloat16(av.x), __float2bfloat16(av.y)};
        __nv_bfloat162 a1 = {__float2bfloat16(av.z), __float2bfloat16(av.w)};
        ((__nv_bfloat162*)(g_phi + (size_t)c * DDIM))[tid * 2]     = p0;
        ((__nv_bfloat162*)(g_phi + (size_t)c * DDIM))[tid * 2 + 1] = p1;
        ((__nv_bfloat162*)(g_ahi + (size_t)c * DDIM))[tid * 2]     = a0;
        ((__nv_bfloat162*)(g_ahi + (size_t)c * DDIM))[tid * 2 + 1] = a1;
        #pragma unroll
        for (int o = 16; o > 0; o >>= 1) {
            sp2 += __shfl_xor_sync(0xFFFFFFFFu, sp2, o);
            spa += __shfl_xor_sync(0xFFFFFFFFu, spa, o);
            sa2 += __shfl_xor_sync(0xFFFFFFFFu, sa2, o);
        }
        if ((tid & 31) == 0) {
            red[0][tid >> 5] = sp2; red[1][tid >> 5] = spa; red[2][tid >> 5] = sa2;
        }
        __syncthreads();
        if (tid == 0) {
            float t0 = 0.f, t1 = 0.f, t2 = 0.f;
            #pragma unroll
            for (int w = 0; w < 8; w++) { t0 += red[0][w]; t1 += red[1][w]; t2 += red[2][w]; }
            g_p2[c] = t0; g_pa[c] = t1; g_an[c] = sqrtf(t2);
        }
    }
}

// ---------------------------------------------------------------------------
// Epilogue math: 1 MUFU (rsqrt), no division, no log.
// ---------------------------------------------------------------------------
__device__ __forceinline__ float hyp_logit(float px, float xa, float x2,
                                           float p2, float pa, float an) {
    const float A   = 1.0f - 2.0f * px + x2;
    const float Bc  = 1.0f - p2;
    const float den = fmaxf(fmaf(x2, p2, fmaf(-2.0f, px, 1.0f)), EPSV);
    const float w   = fmaxf(fmaf(A * A, p2, fmaf(Bc * Bc, x2, -2.0f * A * Bc * px)), 0.0f);
    const float u   = fmaf(Bc, xa, -A * pa);
    const float N   = 2.0f * u * den;
    const float D   = fmaf(den, den, w) * an;
    const float z   = N * rsqrtf(fmaf(N, N, D * D));
    const float t   = z * z;
    float s = 1.0f / 25.0f;
    s = fmaf(s, t, 1.0f / 23.0f); s = fmaf(s, t, 1.0f / 21.0f);
    s = fmaf(s, t, 1.0f / 19.0f); s = fmaf(s, t, 1.0f / 17.0f);
    s = fmaf(s, t, 1.0f / 15.0f); s = fmaf(s, t, 1.0f / 13.0f);
    s = fmaf(s, t, 1.0f / 11.0f); s = fmaf(s, t, 1.0f / 9.0f);
    s = fmaf(s, t, 1.0f / 7.0f);  s = fmaf(s, t, 1.0f / 5.0f);
    s = fmaf(s, t, 1.0f / 3.0f);  s = fmaf(s, t, 1.0f);
    return -z * s;
}

// ---------------------------------------------------------------------------
// Main kernel: dual pure-bf16 GEMM via mma.sync + fused epilogue
//   CTA 128(batch) x 64(class), 256 threads (8 warps: 2m x 4n), 2 CTAs/SM.
//   NEW: mbarrier producer-consumer pipeline (no __syncthreads convoy).
//   full[s]: cp.async completion (count 256). free[s]: consumer last-read
//   arrives (count 256), posted BEFORE the final MMA burst -> cross-warp drift.
// ---------------------------------------------------------------------------
#define BM 128
#define BN 64
#define BK 64
#define NKIT (DDIM / BK)          // 16
#define ROWB 144                  // 128 data + 16 pad (conflict-free ldmatrix)
#define STAGEB (256 * ROWB)       // 36864
#define STG0 128                  // stages start after barrier block
#define SMEM_NEED (STG0 + 3 * STAGEB)  // 110720

__global__ __launch_bounds__(256, 2) void mlr_mma_kernel(float* __restrict__ out) {
    extern __shared__ char sm[];
    const uint32_t sb = smem_u32(sm);
    const int tid  = threadIdx.x;
    const int wid  = tid >> 5;
    const int lane = tid & 31;
    const int wn = wid & 3;
    const int wm = wid >> 2;
    const int cb = blockIdx.x * BN;
    const int rb = blockIdx.y * BM;
    const int rot = wm << 1;       // ks phase rotation: 0 or 2

    // barriers: full[s] at sb + s*8; free[s] at sb + 24 + s*8
    if (tid == 0) {
        #pragma unroll
        for (int s = 0; s < 3; s++) {
            MBARRIER_INIT(sb + s * 8, 256);
            MBARRIER_INIT(sb + 24 + s * 8, 256);
        }
    }
    __syncthreads();

    // loader mapping
    const int lr = tid >> 3;
    const int lch = tid & 7;
    const __nv_bfloat16* xb = g_xhi + (size_t)(rb + lr) * DDIM + lch * 8;
    const __nv_bfloat16* pb = g_phi + (size_t)(cb + lr) * DDIM + lch * 8;
    const __nv_bfloat16* ab = g_ahi + (size_t)(cb + lr) * DDIM + lch * 8;
    const uint32_t ldoff = lr * ROWB + lch * 16;

    #define ISSUE_STAGE(base, ko)                                              \
        do {                                                                   \
            const uint32_t _d = (base) + ldoff;                                \
            CP_ASYNC16(_d,              xb + (ko));                            \
            CP_ASYNC16(_d + 32 * ROWB,  xb + (ko) + (size_t)32 * DDIM);        \
            CP_ASYNC16(_d + 64 * ROWB,  xb + (ko) + (size_t)64 * DDIM);        \
            CP_ASYNC16(_d + 96 * ROWB,  xb + (ko) + (size_t)96 * DDIM);        \
            CP_ASYNC16(_d + 128 * ROWB, pb + (ko));                            \
            CP_ASYNC16(_d + 160 * ROWB, pb + (ko) + (size_t)32 * DDIM);        \
            CP_ASYNC16(_d + 192 * ROWB, ab + (ko));                            \
            CP_ASYNC16(_d + 224 * ROWB, ab + (ko) + (size_t)32 * DDIM);        \
        } while (0)

    // ldmatrix lane mappings
    const int a_r = lane & 15;
    const int a_c = lane >> 4;
    const int b_r = (lane & 7) | ((lane & 16) >> 1);
    const int b_h = (lane >> 3) & 1;
    const uint32_t smA = (wm * 64 + a_r) * ROWB + a_c * 16;
    const uint32_t smP = (128 + wn * 16 + b_r) * ROWB + b_h * 16;
    const uint32_t smQ = (192 + wn * 16 + b_r) * ROWB + b_h * 16;

    float cP[4][2][4];
    float cA[4][2][4];
    #pragma unroll
    for (int mt = 0; mt < 4; mt++)
        #pragma unroll
        for (int nt = 0; nt < 2; nt++)
            #pragma unroll
            for (int i = 0; i < 4; i++) { cP[mt][nt][i] = 0.f; cA[mt][nt][i] = 0.f; }

    // pre-arm free[2] so the k=0 issue wait passes (all 256 threads arrive)
    MB_ARRIVE(sb + 24 + 16);

    // prologue: stages 0 and 1 (full-arrive via cp.async tracking)
    ISSUE_STAGE(sb + STG0 + 0 * STAGEB, 0);
    CPX_ARRIVE(sb + 0);
    ISSUE_STAGE(sb + STG0 + 1 * STAGEB, BK);
    CPX_ARRIVE(sb + 8);

    // One k-iteration. FS = consume slot, IS = issue slot (both compile-time).
    #define KITER(FS, IS, KO2, DO_ISSUE)                                       \
    {                                                                          \
        MBARRIER_WAIT_PARITY(sb + (FS) * 8, pm);                               \
        const uint32_t st = sb + STG0 + (FS) * STAGEB;                         \
        uint32_t bp[2][4], ba[2][4];                                           \
        const uint32_t kof0 = (rot & 3) * 32;                                  \
        LDSM4(bp[0], st + smP + kof0);                                         \
        LDSM4(ba[0], st + smQ + kof0);                                         \
        _Pragma("unroll")                                                      \
        for (int ks = 0; ks < 4; ks++) {                                       \
            const int cur = ks & 1;                                            \
            const uint32_t kofs = ((ks + rot) & 3) * 32;                       \
            uint32_t xh[4][4];                                                 \
            _Pragma("unroll")                                                  \
            for (int mt = 0; mt < 4; mt++)                                     \
                LDSM4(xh[mt], st + smA + mt * 16 * ROWB + kofs);               \
            if (ks == 3) MB_ARRIVE(sb + 24 + (FS) * 8);  /* last read done */  \
            if (ks < 3) {                                                      \
                const uint32_t knx = ((ks + 1 + rot) & 3) * 32;                \
                LDSM4(bp[cur ^ 1], st + smP + knx);                            \
                LDSM4(ba[cur ^ 1], st + smQ + knx);                            \
            }                                                                  \
            if ((DO_ISSUE) && ks == 1) {                                       \
                MBARRIER_WAIT_PARITY(sb + 24 + (IS) * 8, pm);                  \
                ISSUE_STAGE(sb + STG0 + (IS) * STAGEB, KO2);                   \
                CPX_ARRIVE(sb + (IS) * 8);                                     \
            }                                                                  \
            _Pragma("unroll")                                                  \
            for (int mt = 0; mt < 4; mt++) {                                   \
                _Pragma("unroll")                                              \
                for (int nt = 0; nt < 2; nt++) {                               \
                    MMA16816(cP[mt][nt], xh[mt], bp[cur][nt * 2], bp[cur][nt * 2 + 1]); \
                    MMA16816(cA[mt][nt], xh[mt], ba[cur][nt * 2], ba[cur][nt * 2 + 1]); \
                }                                                              \
            }                                                                  \
        }                                                                      \
    }

    uint32_t pm = 0;
    size_t kb = 0;
    #pragma unroll 1
    for (int m = 0; m < 5; m++) {      // k = 3m, 3m+1, 3m+2 (k = 0..14)
        KITER(0, 2, kb + 2 * BK, true);
        KITER(1, 0, kb + 3 * BK, true);
        KITER(2, 1, kb + 4 * BK, true);
        pm ^= 1;
        kb += 3 * BK;
    }
    KITER(0, 2, 0, false);             // k = 15, no issue

    // epilogue (registers only; no smem dependency -> no sync)
    const int g  = lane >> 2;
    const int tg = lane & 3;
    #pragma unroll
    for (int mt = 0; mt < 4; mt++) {
        #pragma unroll
        for (int h = 0; h < 2; h++) {
            const int row = rb + wm * 64 + mt * 16 + h * 8 + g;
            const float x2 = g_x2[row];
            float* orow = out + (size_t)row * CDIM + cb + wn * 16;
            #pragma unroll
            for (int nt = 0; nt < 2; nt++) {
                const int col = cb + wn * 16 + nt * 8 + tg * 2;
                float2 r;
                r.x = hyp_logit(cP[mt][nt][2 * h],     cA[mt][nt][2 * h],     x2,
                                g_p2[col],     g_pa[col],     g_an[col]);
                r.y = hyp_logit(cP[mt][nt][2 * h + 1], cA[mt][nt][2 * h + 1], x2,
                                g_p2[col + 1], g_pa[col + 1], g_an[col + 1]);
                *(float2*)(orow + nt * 8 + tg * 2) = r;
            }
        }
    }
    #undef KITER
    #undef ISSUE_STAGE
}

// ---------------------------------------------------------------------------
extern "C" void kernel_launch(void* const* d_in, const int* in_sizes, int n_in,
                              void* d_out, int out_size) {
    const float* x = (const float*)d_in[0];
    const float* a = (const float*)d_in[1];
    const float* p = (const float*)d_in[2];
    float* out = (float*)d_out;

    cudaFuncSetAttribute(mlr_mma_kernel,
                         cudaFuncAttributeMaxDynamicSharedMemorySize, SMEM_NEED);

    prep_kernel<<<BDIM + CDIM, 256>>>(x, a, p);
    dim3 grid(CDIM / BN, BDIM / BM);
    mlr_mma_kernel<<<grid, 256, SMEM_NEED>>>(out);
}

// round 11
// speedup vs baseline: 1.2039x; 1.0606x over previous
#include <cuda_runtime.h>
#include <cuda_bf16.h>
#include <math.h>
#include <cstdint>

// Fixed shapes for HyperbolicMLR_33045478375870
#define BDIM 4096
#define DDIM 1024
#define CDIM 4096
#define EPSV 1e-15f
#define MAXN 0.99999f   // (1 - 1e-5)/sqrt(c), c = 1

// ---------------------------------------------------------------------------
// Device scratch (no allocations allowed)
// ---------------------------------------------------------------------------
__device__ __nv_bfloat16 g_xhi[(size_t)BDIM * DDIM];
__device__ __nv_bfloat16 g_phi[(size_t)CDIM * DDIM];
__device__ __nv_bfloat16 g_ahi[(size_t)CDIM * DDIM];
__device__ float g_x2[BDIM];
__device__ float g_p2[CDIM];
__device__ float g_pa[CDIM];
__device__ float g_an[CDIM];

// ---------------------------------------------------------------------------
__device__ __forceinline__ uint32_t smem_u32(const void* p) {
    uint32_t a;
    asm("{ .reg .u64 t; cvta.to.shared.u64 t, %1; cvt.u32.u64 %0, t; }"
        : "=r"(a) : "l"(p));
    return a;
}

#define LDSM4(r, addr) \
    asm volatile("ldmatrix.sync.aligned.m8n8.x4.shared.b16 {%0,%1,%2,%3}, [%4];" \
                 : "=r"((r)[0]), "=r"((r)[1]), "=r"((r)[2]), "=r"((r)[3]) \
                 : "r"(addr))

#define MMA16816(c, a, b0, b1) \
    asm volatile("mma.sync.aligned.m16n8k16.row.col.f32.bf16.bf16.f32 " \
                 "{%0,%1,%2,%3},{%4,%5,%6,%7},{%8,%9},{%0,%1,%2,%3};" \
                 : "+f"((c)[0]), "+f"((c)[1]), "+f"((c)[2]), "+f"((c)[3]) \
                 : "r"((a)[0]), "r"((a)[1]), "r"((a)[2]), "r"((a)[3]), \
                   "r"(b0), "r"(b1))

#define CP_ASYNC16(dst, src) \
    asm volatile("cp.async.cg.shared.global [%0], [%1], 16;" \
                 :: "r"(dst), "l"(__cvta_generic_to_global(src)))

#define MBARRIER_INIT(mbar, count) \
    asm volatile("mbarrier.init.shared.b64 [%0], %1;" \
                 :: "r"((uint32_t)(mbar)), "r"((uint32_t)(count)) : "memory")

#define MB_ARRIVE(mbar) \
    asm volatile("mbarrier.arrive.shared.b64 _, [%0];" \
                 :: "r"((uint32_t)(mbar)) : "memory")

#define CPX_ARRIVE(mbar) \
    asm volatile("cp.async.mbarrier.arrive.noinc.shared.b64 [%0];" \
                 :: "r"((uint32_t)(mbar)) : "memory")

#define MBARRIER_WAIT_PARITY(mbar, parity) do {                                   \
    uint32_t _mbar = (uint32_t)(mbar);                                            \
    uint32_t _par  = (uint32_t)(parity);                                          \
    uint32_t _done;                                                               \
    asm volatile(                                                                 \
        "{\n\t.reg .pred p;\n\t"                                                  \
        "mbarrier.try_wait.parity.acquire.cta.shared::cta.b64 p, [%1], %2;\n\t"   \
        "selp.b32 %0, 1, 0, p;\n\t}"                                              \
        : "=r"(_done) : "r"(_mbar), "r"(_par) : "memory");                        \
    if (!_done) {                                                                 \
        asm volatile(                                                             \
            "{\n\t.reg .pred P1;\n\t"                                             \
            "WAIT_LOOP_%=:\n\t"                                                   \
            "mbarrier.try_wait.parity.acquire.cta.shared::cta.b64 P1, [%0], %1, 0x989680;\n\t" \
            "@P1 bra.uni WAIT_DONE_%=;\n\t"                                       \
            "bra.uni WAIT_LOOP_%=;\n\t"                                           \
            "WAIT_DONE_%=:\n\t}"                                                  \
            :: "r"(_mbar), "r"(_par) : "memory");                                 \
    }                                                                             \
} while (0)

// ---------------------------------------------------------------------------
// Merged prep kernel (unchanged)
// ---------------------------------------------------------------------------
__global__ __launch_bounds__(256) void prep_kernel(const float* __restrict__ x,
                                                   const float* __restrict__ a,
                                                   const float* __restrict__ p) {
    const int blk = blockIdx.x;
    const int tid = threadIdx.x;
    __shared__ float red[3][8];

    if (blk < BDIM) {
        const int b = blk;
        const float4 v = ((const float4*)(x + (size_t)b * DDIM))[tid];
        float s = v.x * v.x + v.y * v.y + v.z * v.z + v.w * v.w;
        #pragma unroll
        for (int o = 16; o > 0; o >>= 1) s += __shfl_xor_sync(0xFFFFFFFFu, s, o);
        if ((tid & 31) == 0) red[0][tid >> 5] = s;
        __syncthreads();
        __shared__ float sh_scale;
        if (tid == 0) {
            float tot = 0.f;
            #pragma unroll
            for (int w = 0; w < 8; w++) tot += red[0][w];
            float xn = fmaxf(sqrtf(tot), EPSV);
            float scale = (xn > MAXN) ? (MAXN / xn) : 1.0f;
            sh_scale = scale;
            g_x2[b] = tot * scale * scale;
        }
        __syncthreads();
        const float sc = sh_scale;
        __nv_bfloat162 o0 = {__float2bfloat16(v.x * sc), __float2bfloat16(v.y * sc)};
        __nv_bfloat162 o1 = {__float2bfloat16(v.z * sc), __float2bfloat16(v.w * sc)};
        ((__nv_bfloat162*)(g_xhi + (size_t)b * DDIM))[tid * 2]     = o0;
        ((__nv_bfloat162*)(g_xhi + (size_t)b * DDIM))[tid * 2 + 1] = o1;
    } else {
        const int c = blk - BDIM;
        const float4 pv = ((const float4*)(p + (size_t)c * DDIM))[tid];
        const float4 av = ((const float4*)(a + (size_t)c * DDIM))[tid];
        float sp2 = pv.x * pv.x + pv.y * pv.y + pv.z * pv.z + pv.w * pv.w;
        float spa = pv.x * av.x + pv.y * av.y + pv.z * av.z + pv.w * av.w;
        float sa2 = av.x * av.x + av.y * av.y + av.z * av.z + av.w * av.w;
        __nv_bfloat162 p0 = {__float2bfloat16(pv.x), __float2bfloat16(pv.y)};
        __nv_bfloat162 p1 = {__float2bfloat16(pv.z), __float2bfloat16(pv.w)};
        __nv_bfloat162 a0 = {__float2bfloat16(av.x), __float2bfloat16(av.y)};
        __nv_bfloat162 a1 = {__float2bfloat16(av.z), __float2bfloat16(av.w)};
        ((__nv_bfloat162*)(g_phi + (size_t)c * DDIM))[tid * 2]     = p0;
        ((__nv_bfloat162*)(g_phi + (size_t)c * DDIM))[tid * 2 + 1] = p1;
        ((__nv_bfloat162*)(g_ahi + (size_t)c * DDIM))[tid * 2]     = a0;
        ((__nv_bfloat162*)(g_ahi + (size_t)c * DDIM))[tid * 2 + 1] = a1;
        #pragma unroll
        for (int o = 16; o > 0; o >>= 1) {
            sp2 += __shfl_xor_sync(0xFFFFFFFFu, sp2, o);
            spa += __shfl_xor_sync(0xFFFFFFFFu, spa, o);
            sa2 += __shfl_xor_sync(0xFFFFFFFFu, sa2, o);
        }
        if ((tid & 31) == 0) {
            red[0][tid >> 5] = sp2; red[1][tid >> 5] = spa; red[2][tid >> 5] = sa2;
        }
        __syncthreads();
        if (tid == 0) {
            float t0 = 0.f, t1 = 0.f, t2 = 0.f;
            #pragma unroll
            for (int w = 0; w < 8; w++) { t0 += red[0][w]; t1 += red[1][w]; t2 += red[2][w]; }
            g_p2[c] = t0; g_pa[c] = t1; g_an[c] = sqrtf(t2);
        }
    }
}

// ---------------------------------------------------------------------------
// Epilogue math: 1 MUFU (rsqrt), no division, no log.
// ---------------------------------------------------------------------------
__device__ __forceinline__ float hyp_logit(float px, float xa, float x2,
                                           float p2, float pa, float an) {
    const float A   = 1.0f - 2.0f * px + x2;
    const float Bc  = 1.0f - p2;
    const float den = fmaxf(fmaf(x2, p2, fmaf(-2.0f, px, 1.0f)), EPSV);
    const float w   = fmaxf(fmaf(A * A, p2, fmaf(Bc * Bc, x2, -2.0f * A * Bc * px)), 0.0f);
    const float u   = fmaf(Bc, xa, -A * pa);
    const float N   = 2.0f * u * den;
    const float D   = fmaf(den, den, w) * an;
    const float z   = N * rsqrtf(fmaf(N, N, D * D));
    const float t   = z * z;
    float s = 1.0f / 25.0f;
    s = fmaf(s, t, 1.0f / 23.0f); s = fmaf(s, t, 1.0f / 21.0f);
    s = fmaf(s, t, 1.0f / 19.0f); s = fmaf(s, t, 1.0f / 17.0f);
    s = fmaf(s, t, 1.0f / 15.0f); s = fmaf(s, t, 1.0f / 13.0f);
    s = fmaf(s, t, 1.0f / 11.0f); s = fmaf(s, t, 1.0f / 9.0f);
    s = fmaf(s, t, 1.0f / 7.0f);  s = fmaf(s, t, 1.0f / 5.0f);
    s = fmaf(s, t, 1.0f / 3.0f);  s = fmaf(s, t, 1.0f);
    return -z * s;
}

// ---------------------------------------------------------------------------
// Main kernel: dual pure-bf16 GEMM via mma.sync + fused epilogue
//   CTA 128x64, 256 threads (8 warps 2m x 4n), 2 CTAs/SM, mbarrier pipeline.
//   NEW vs R10: cross-iteration B-fragment prefetch (full-wait hoisted to
//   prior iter ks==2; bp/ba[0] of next stage loaded at ks==3), 4-phase warp
//   rotation, split cp.async issue (x at ks==1, p/a at ks==2).
// ---------------------------------------------------------------------------
#define BM 128
#define BN 64
#define BK 64
#define NKIT (DDIM / BK)          // 16
#define ROWB 144                  // 128 data + 16 pad (conflict-free ldmatrix)
#define STAGEB (256 * ROWB)       // 36864
#define STG0 128
#define SMEM_NEED (STG0 + 3 * STAGEB)  // 110720

__global__ __launch_bounds__(256, 2) void mlr_mma_kernel(float* __restrict__ out) {
    extern __shared__ char sm[];
    const uint32_t sb = smem_u32(sm);
    const int tid  = threadIdx.x;
    const int wid  = tid >> 5;
    const int lane = tid & 31;
    const int wn = wid & 3;
    const int wm = wid >> 2;
    const int cb = blockIdx.x * BN;
    const int rb = blockIdx.y * BM;
    const int rot = (wn + (wm << 1)) & 3;   // 4-phase SM-wide spread

    // barriers: full[s] at sb + s*8; free[s] at sb + 24 + s*8
    if (tid == 0) {
        #pragma unroll
        for (int s = 0; s < 3; s++) {
            MBARRIER_INIT(sb + s * 8, 256);
            MBARRIER_INIT(sb + 24 + s * 8, 256);
        }
    }
    __syncthreads();

    // loader mapping
    const int lr = tid >> 3;
    const int lch = tid & 7;
    const __nv_bfloat16* xb = g_xhi + (size_t)(rb + lr) * DDIM + lch * 8;
    const __nv_bfloat16* pb = g_phi + (size_t)(cb + lr) * DDIM + lch * 8;
    const __nv_bfloat16* ab = g_ahi + (size_t)(cb + lr) * DDIM + lch * 8;
    const uint32_t ldoff = lr * ROWB + lch * 16;

    #define ISSUE_X(base, ko)                                                  \
        do {                                                                   \
            const uint32_t _d = (base) + ldoff;                                \
            CP_ASYNC16(_d,              xb + (ko));                            \
            CP_ASYNC16(_d + 32 * ROWB,  xb + (ko) + (size_t)32 * DDIM);        \
            CP_ASYNC16(_d + 64 * ROWB,  xb + (ko) + (size_t)64 * DDIM);        \
            CP_ASYNC16(_d + 96 * ROWB,  xb + (ko) + (size_t)96 * DDIM);        \
        } while (0)
    #define ISSUE_PA(base, ko)                                                 \
        do {                                                                   \
            const uint32_t _d = (base) + ldoff;                                \
            CP_ASYNC16(_d + 128 * ROWB, pb + (ko));                            \
            CP_ASYNC16(_d + 160 * ROWB, pb + (ko) + (size_t)32 * DDIM);        \
            CP_ASYNC16(_d + 192 * ROWB, ab + (ko));                            \
            CP_ASYNC16(_d + 224 * ROWB, ab + (ko) + (size_t)32 * DDIM);        \
        } while (0)

    // ldmatrix lane mappings
    const int a_r = lane & 15;
    const int a_c = lane >> 4;
    const int b_r = (lane & 7) | ((lane & 16) >> 1);
    const int b_h = (lane >> 3) & 1;
    const uint32_t smA = (wm * 64 + a_r) * ROWB + a_c * 16;
    const uint32_t smP = (128 + wn * 16 + b_r) * ROWB + b_h * 16;
    const uint32_t smQ = (192 + wn * 16 + b_r) * ROWB + b_h * 16;
    const uint32_t kof0 = (rot & 3) * 32;

    float cP[4][2][4];
    float cA[4][2][4];
    #pragma unroll
    for (int mt = 0; mt < 4; mt++)
        #pragma unroll
        for (int nt = 0; nt < 2; nt++)
            #pragma unroll
            for (int i = 0; i < 4; i++) { cP[mt][nt][i] = 0.f; cA[mt][nt][i] = 0.f; }

    // pre-arm free[2]
    MB_ARRIVE(sb + 24 + 16);

    // prologue: stages 0 and 1; wait stage 0 and preload first B frags
    ISSUE_X(sb + STG0, 0);             ISSUE_PA(sb + STG0, 0);
    CPX_ARRIVE(sb + 0);
    ISSUE_X(sb + STG0 + STAGEB, BK);   ISSUE_PA(sb + STG0 + STAGEB, BK);
    CPX_ARRIVE(sb + 8);

    uint32_t bp[2][4], ba[2][4];
    MBARRIER_WAIT_PARITY(sb + 0, 0);
    LDSM4(bp[0], sb + STG0 + smP + kof0);
    LDSM4(ba[0], sb + STG0 + smQ + kof0);

    // One k-iteration. FS=consume slot, IS=issue slot, NS=next slot.
    // full[FS] was waited by the PREVIOUS iteration (ks==2); bp/ba[0] of FS
    // were preloaded by the previous iteration (ks==3).
    #define KITER(FS, IS, NS, KO2, DO_ISSUE, DO_NEXT, NPAR)                    \
    {                                                                          \
        const uint32_t st  = sb + STG0 + (FS) * STAGEB;                        \
        const uint32_t stn = sb + STG0 + (NS) * STAGEB;                        \
        _Pragma("unroll")                                                      \
        for (int ks = 0; ks < 4; ks++) {                                       \
            const int cur = ks & 1;                                            \
            const uint32_t kofs = ((ks + rot) & 3) * 32;                       \
            uint32_t xh[4][4];                                                 \
            _Pragma("unroll")                                                  \
            for (int mt = 0; mt < 4; mt++)                                     \
                LDSM4(xh[mt], st + smA + mt * 16 * ROWB + kofs);               \
            if (ks == 3) MB_ARRIVE(sb + 24 + (FS) * 8);  /* stage FS free */   \
            if (ks < 3) {                                                      \
                const uint32_t knx = ((ks + 1 + rot) & 3) * 32;                \
                LDSM4(bp[cur ^ 1], st + smP + knx);                            \
                LDSM4(ba[cur ^ 1], st + smQ + knx);                            \
            }                                                                  \
            if ((DO_ISSUE) && ks == 1) {                                       \
                MBARRIER_WAIT_PARITY(sb + 24 + (IS) * 8, pm);                  \
                ISSUE_X(sb + STG0 + (IS) * STAGEB, KO2);                       \
            }                                                                  \
            if ((DO_ISSUE) && ks == 2) {                                       \
                ISSUE_PA(sb + STG0 + (IS) * STAGEB, KO2);                      \
                CPX_ARRIVE(sb + (IS) * 8);                                     \
            }                                                                  \
            if ((DO_NEXT) && ks == 2)                                          \
                MBARRIER_WAIT_PARITY(sb + (NS) * 8, NPAR);                     \
            if ((DO_NEXT) && ks == 3) {                                        \
                LDSM4(bp[0], stn + smP + kof0);                                \
                LDSM4(ba[0], stn + smQ + kof0);                                \
            }                                                                  \
            _Pragma("unroll")                                                  \
            for (int mt = 0; mt < 4; mt++) {                                   \
                _Pragma("unroll")                                              \
                for (int nt = 0; nt < 2; nt++) {                               \
                    MMA16816(cP[mt][nt], xh[mt], bp[cur][nt * 2], bp[cur][nt * 2 + 1]); \
                    MMA16816(cA[mt][nt], xh[mt], ba[cur][nt * 2], ba[cur][nt * 2 + 1]); \
                }                                                              \
            }                                                                  \
        }                                                                      \
    }

    uint32_t pm = 0;
    size_t kb = 0;
    #pragma unroll 1
    for (int m = 0; m < 5; m++) {      // k = 3m .. 3m+2 (k = 0..14)
        KITER(0, 2, 1, kb + 2 * BK, true, true, pm);
        KITER(1, 0, 2, kb + 3 * BK, true, true, pm);
        KITER(2, 1, 0, kb + 4 * BK, true, true, pm ^ 1);
        pm ^= 1;
        kb += 3 * BK;
    }
    KITER(0, 2, 1, 0, false, false, pm);   // k = 15

    // epilogue (registers only)
    const int g  = lane >> 2;
    const int tg = lane & 3;
    #pragma unroll
    for (int mt = 0; mt < 4; mt++) {
        #pragma unroll
        for (int h = 0; h < 2; h++) {
            const int row = rb + wm * 64 + mt * 16 + h * 8 + g;
            const float x2 = g_x2[row];
            float* orow = out + (size_t)row * CDIM + cb + wn * 16;
            #pragma unroll
            for (int nt = 0; nt < 2; nt++) {
                const int col = cb + wn * 16 + nt * 8 + tg * 2;
                float2 r;
                r.x = hyp_logit(cP[mt][nt][2 * h],     cA[mt][nt][2 * h],     x2,
                                g_p2[col],     g_pa[col],     g_an[col]);
                r.y = hyp_logit(cP[mt][nt][2 * h + 1], cA[mt][nt][2 * h + 1], x2,
                                g_p2[col + 1], g_pa[col + 1], g_an[col + 1]);
                *(float2*)(orow + nt * 8 + tg * 2) = r;
            }
        }
    }
    #undef KITER
    #undef ISSUE_X
    #undef ISSUE_PA
}

// ---------------------------------------------------------------------------
extern "C" void kernel_launch(void* const* d_in, const int* in_sizes, int n_in,
                              void* d_out, int out_size) {
    const float* x = (const float*)d_in[0];
    const float* a = (const float*)d_in[1];
    const float* p = (const float*)d_in[2];
    float* out = (float*)d_out;

    cudaFuncSetAttribute(mlr_mma_kernel,
                         cudaFuncAttributeMaxDynamicSharedMemorySize, SMEM_NEED);

    prep_kernel<<<BDIM + CDIM, 256>>>(x, a, p);
    dim3 grid(CDIM / BN, BDIM / BM);
    mlr_mma_kernel<<<grid, 256, SMEM_NEED>>>(out);
}

// round 12
// speedup vs baseline: 1.2325x; 1.0238x over previous
#include <cuda_runtime.h>
#include <cuda_bf16.h>
#include <math.h>
#include <cstdint>

// Fixed shapes for HyperbolicMLR_33045478375870
#define BDIM 4096
#define DDIM 1024
#define CDIM 4096
#define EPSV 1e-15f
#define MAXN 0.99999f   // (1 - 1e-5)/sqrt(c), c = 1

// ---------------------------------------------------------------------------
// Device scratch (no allocations allowed)
// ---------------------------------------------------------------------------
__device__ __nv_bfloat16 g_xhi[(size_t)BDIM * DDIM];
__device__ __nv_bfloat16 g_phi[(size_t)CDIM * DDIM];
__device__ __nv_bfloat16 g_ahi[(size_t)CDIM * DDIM];
__device__ float g_x2[BDIM];
__device__ float g_p2[CDIM];
__device__ float g_pa[CDIM];
__device__ float g_an[CDIM];

// ---------------------------------------------------------------------------
__device__ __forceinline__ uint32_t smem_u32(const void* p) {
    uint32_t a;
    asm("{ .reg .u64 t; cvta.to.shared.u64 t, %1; cvt.u32.u64 %0, t; }"
        : "=r"(a) : "l"(p));
    return a;
}

#define LDSM4(r, addr) \
    asm volatile("ldmatrix.sync.aligned.m8n8.x4.shared.b16 {%0,%1,%2,%3}, [%4];" \
                 : "=r"((r)[0]), "=r"((r)[1]), "=r"((r)[2]), "=r"((r)[3]) \
                 : "r"(addr))

#define MMA16816(c, a, b0, b1) \
    asm volatile("mma.sync.aligned.m16n8k16.row.col.f32.bf16.bf16.f32 " \
                 "{%0,%1,%2,%3},{%4,%5,%6,%7},{%8,%9},{%0,%1,%2,%3};" \
                 : "+f"((c)[0]), "+f"((c)[1]), "+f"((c)[2]), "+f"((c)[3]) \
                 : "r"((a)[0]), "r"((a)[1]), "r"((a)[2]), "r"((a)[3]), \
                   "r"(b0), "r"(b1))

#define CP_ASYNC16(dst, src) \
    asm volatile("cp.async.cg.shared.global [%0], [%1], 16;" \
                 :: "r"(dst), "l"(__cvta_generic_to_global(src)))

#define MBARRIER_INIT(mbar, count) \
    asm volatile("mbarrier.init.shared.b64 [%0], %1;" \
                 :: "r"((uint32_t)(mbar)), "r"((uint32_t)(count)) : "memory")

#define MB_ARRIVE(mbar) \
    asm volatile("mbarrier.arrive.shared.b64 _, [%0];" \
                 :: "r"((uint32_t)(mbar)) : "memory")

#define CPX_ARRIVE(mbar) \
    asm volatile("cp.async.mbarrier.arrive.noinc.shared.b64 [%0];" \
                 :: "r"((uint32_t)(mbar)) : "memory")

#define MBARRIER_WAIT_PARITY(mbar, parity) do {                                   \
    uint32_t _mbar = (uint32_t)(mbar);                                            \
    uint32_t _par  = (uint32_t)(parity);                                          \
    uint32_t _done;                                                               \
    asm volatile(                                                                 \
        "{\n\t.reg .pred p;\n\t"                                                  \
        "mbarrier.try_wait.parity.acquire.cta.shared::cta.b64 p, [%1], %2;\n\t"   \
        "selp.b32 %0, 1, 0, p;\n\t}"                                              \
        : "=r"(_done) : "r"(_mbar), "r"(_par) : "memory");                        \
    if (!_done) {                                                                 \
        asm volatile(                                                             \
            "{\n\t.reg .pred P1;\n\t"                                             \
            "WAIT_LOOP_%=:\n\t"                                                   \
            "mbarrier.try_wait.parity.acquire.cta.shared::cta.b64 P1, [%0], %1, 0x989680;\n\t" \
            "@P1 bra.uni WAIT_DONE_%=;\n\t"                                       \
            "bra.uni WAIT_LOOP_%=;\n\t"                                           \
            "WAIT_DONE_%=:\n\t}"                                                  \
            :: "r"(_mbar), "r"(_par) : "memory");                                 \
    }                                                                             \
} while (0)

// Producer wait: post-wait accesses are async-proxy (cp.async) only -> relaxed.
#define MBARRIER_WAIT_PARITY_RELAXED(mbar, parity) do {                           \
    uint32_t _mbar = (uint32_t)(mbar);                                            \
    uint32_t _par  = (uint32_t)(parity);                                          \
    uint32_t _done;                                                               \
    asm volatile(                                                                 \
        "{\n\t.reg .pred p;\n\t"                                                  \
        "mbarrier.try_wait.parity.relaxed.cta.shared::cta.b64 p, [%1], %2;\n\t"   \
        "selp.b32 %0, 1, 0, p;\n\t}"                                              \
        : "=r"(_done) : "r"(_mbar), "r"(_par) : "memory");                        \
    if (!_done) {                                                                 \
        asm volatile(                                                             \
            "{\n\t.reg .pred P1;\n\t"                                             \
            "WAIT_LOOP_%=:\n\t"                                                   \
            "mbarrier.try_wait.parity.relaxed.cta.shared::cta.b64 P1, [%0], %1, 0x989680;\n\t" \
            "@P1 bra.uni WAIT_DONE_%=;\n\t"                                       \
            "bra.uni WAIT_LOOP_%=;\n\t"                                           \
            "WAIT_DONE_%=:\n\t}"                                                  \
            :: "r"(_mbar), "r"(_par) : "memory");                                 \
    }                                                                             \
} while (0)

// ---------------------------------------------------------------------------
// Merged prep kernel (unchanged)
// ---------------------------------------------------------------------------
__global__ __launch_bounds__(256) void prep_kernel(const float* __restrict__ x,
                                                   const float* __restrict__ a,
                                                   const float* __restrict__ p) {
    const int blk = blockIdx.x;
    const int tid = threadIdx.x;
    __shared__ float red[3][8];

    if (blk < BDIM) {
        const int b = blk;
        const float4 v = ((const float4*)(x + (size_t)b * DDIM))[tid];
        float s = v.x * v.x + v.y * v.y + v.z * v.z + v.w * v.w;
        #pragma unroll
        for (int o = 16; o > 0; o >>= 1) s += __shfl_xor_sync(0xFFFFFFFFu, s, o);
        if ((tid & 31) == 0) red[0][tid >> 5] = s;
        __syncthreads();
        __shared__ float sh_scale;
        if (tid == 0) {
            float tot = 0.f;
            #pragma unroll
            for (int w = 0; w < 8; w++) tot += red[0][w];
            float xn = fmaxf(sqrtf(tot), EPSV);
            float scale = (xn > MAXN) ? (MAXN / xn) : 1.0f;
            sh_scale = scale;
            g_x2[b] = tot * scale * scale;
        }
        __syncthreads();
        const float sc = sh_scale;
        __nv_bfloat162 o0 = {__float2bfloat16(v.x * sc), __float2bfloat16(v.y * sc)};
        __nv_bfloat162 o1 = {__float2bfloat16(v.z * sc), __float2bfloat16(v.w * sc)};
        ((__nv_bfloat162*)(g_xhi + (size_t)b * DDIM))[tid * 2]     = o0;
        ((__nv_bfloat162*)(g_xhi + (size_t)b * DDIM))[tid * 2 + 1] = o1;
    } else {
        const int c = blk - BDIM;
        const float4 pv = ((const float4*)(p + (size_t)c * DDIM))[tid];
        const float4 av = ((const float4*)(a + (size_t)c * DDIM))[tid];
        float sp2 = pv.x * pv.x + pv.y * pv.y + pv.z * pv.z + pv.w * pv.w;
        float spa = pv.x * av.x + pv.y * av.y + pv.z * av.z + pv.w * av.w;
        float sa2 = av.x * av.x + av.y * av.y + av.z * av.z + av.w * av.w;
        __nv_bfloat162 p0 = {__float2bfloat16(pv.x), __float2bfloat16(pv.y)};
        __nv_bfloat162 p1 = {__float2bfloat16(pv.z), __float2bfloat16(pv.w)};
        __nv_bfloat162 a0 = {__float2bfloat16(av.x), __float2bfloat16(av.y)};
        __nv_bfloat162 a1 = {__float2bfloat16(av.z), __float2bfloat16(av.w)};
        ((__nv_bfloat162*)(g_phi + (size_t)c * DDIM))[tid * 2]     = p0;
        ((__nv_bfloat162*)(g_phi + (size_t)c * DDIM))[tid * 2 + 1] = p1;
        ((__nv_bfloat162*)(g_ahi + (size_t)c * DDIM))[tid * 2]     = a0;
        ((__nv_bfloat162*)(g_ahi + (size_t)c * DDIM))[tid * 2 + 1] = a1;
        #pragma unroll
        for (int o = 16; o > 0; o >>= 1) {
            sp2 += __shfl_xor_sync(0xFFFFFFFFu, sp2, o);
            spa += __shfl_xor_sync(0xFFFFFFFFu, spa, o);
            sa2 += __shfl_xor_sync(0xFFFFFFFFu, sa2, o);
        }
        if ((tid & 31) == 0) {
            red[0][tid >> 5] = sp2; red[1][tid >> 5] = spa; red[2][tid >> 5] = sa2;
        }
        __syncthreads();
        if (tid == 0) {
            float t0 = 0.f, t1 = 0.f, t2 = 0.f;
            #pragma unroll
            for (int w = 0; w < 8; w++) { t0 += red[0][w]; t1 += red[1][w]; t2 += red[2][w]; }
            g_p2[c] = t0; g_pa[c] = t1; g_an[c] = sqrtf(t2);
        }
    }
}

// ---------------------------------------------------------------------------
// Epilogue math: 1 MUFU (rsqrt), no division, no log. 10-term atanh poly
// (tail < 7.7e-5 worst-case rel; negligible vs 2.5e-4 GEMM truncation).
// ---------------------------------------------------------------------------
__device__ __forceinline__ float hyp_logit(float px, float xa, float x2,
                                           float p2, float pa, float an) {
    const float A   = 1.0f - 2.0f * px + x2;
    const float Bc  = 1.0f - p2;
    const float den = fmaxf(fmaf(x2, p2, fmaf(-2.0f, px, 1.0f)), EPSV);
    const float w   = fmaxf(fmaf(A * A, p2, fmaf(Bc * Bc, x2, -2.0f * A * Bc * px)), 0.0f);
    const float u   = fmaf(Bc, xa, -A * pa);
    const float N   = 2.0f * u * den;
    const float D   = fmaf(den, den, w) * an;
    const float z   = N * rsqrtf(fmaf(N, N, D * D));
    const float t   = z * z;
    float s = 1.0f / 19.0f;
    s = fmaf(s, t, 1.0f / 17.0f);
    s = fmaf(s, t, 1.0f / 15.0f); s = fmaf(s, t, 1.0f / 13.0f);
    s = fmaf(s, t, 1.0f / 11.0f); s = fmaf(s, t, 1.0f / 9.0f);
    s = fmaf(s, t, 1.0f / 7.0f);  s = fmaf(s, t, 1.0f / 5.0f);
    s = fmaf(s, t, 1.0f / 3.0f);  s = fmaf(s, t, 1.0f);
    return -z * s;
}

// ---------------------------------------------------------------------------
// Main kernel: dual pure-bf16 GEMM via mma.sync + fused epilogue
//   CTA 128x64, 256 threads (8 warps 2m x 4n), 2 CTAs/SM, mbarrier pipeline,
//   cross-iteration B prefetch, 4-phase warp rotation.
//   NEW vs R11: rolling 2-deep A-fragment buffer (frees 8 regs), relaxed
//   producer wait, trimmed epilogue with hoisted scalars.
// ---------------------------------------------------------------------------
#define BM 128
#define BN 64
#define BK 64
#define NKIT (DDIM / BK)          // 16
#define ROWB 144                  // 128 data + 16 pad (conflict-free ldmatrix)
#define STAGEB (256 * ROWB)       // 36864
#define STG0 128
#define SMEM_NEED (STG0 + 3 * STAGEB)  // 110720

__global__ __launch_bounds__(256, 2) void mlr_mma_kernel(float* __restrict__ out) {
    extern __shared__ char sm[];
    const uint32_t sb = smem_u32(sm);
    const int tid  = threadIdx.x;
    const int wid  = tid >> 5;
    const int lane = tid & 31;
    const int wn = wid & 3;
    const int wm = wid >> 2;
    const int cb = blockIdx.x * BN;
    const int rb = blockIdx.y * BM;
    const int rot = (wn + (wm << 1)) & 3;   // 4-phase SM-wide spread

    // barriers: full[s] at sb + s*8; free[s] at sb + 24 + s*8
    if (tid == 0) {
        #pragma unroll
        for (int s = 0; s < 3; s++) {
            MBARRIER_INIT(sb + s * 8, 256);
            MBARRIER_INIT(sb + 24 + s * 8, 256);
        }
    }
    __syncthreads();

    // loader mapping
    const int lr = tid >> 3;
    const int lch = tid & 7;
    const __nv_bfloat16* xb = g_xhi + (size_t)(rb + lr) * DDIM + lch * 8;
    const __nv_bfloat16* pb = g_phi + (size_t)(cb + lr) * DDIM + lch * 8;
    const __nv_bfloat16* ab = g_ahi + (size_t)(cb + lr) * DDIM + lch * 8;
    const uint32_t ldoff = lr * ROWB + lch * 16;

    #define ISSUE_X(base, ko)                                                  \
        do {                                                                   \
            const uint32_t _d = (base) + ldoff;                                \
            CP_ASYNC16(_d,              xb + (ko));                            \
            CP_ASYNC16(_d + 32 * ROWB,  xb + (ko) + (size_t)32 * DDIM);        \
            CP_ASYNC16(_d + 64 * ROWB,  xb + (ko) + (size_t)64 * DDIM);        \
            CP_ASYNC16(_d + 96 * ROWB,  xb + (ko) + (size_t)96 * DDIM);        \
        } while (0)
    #define ISSUE_PA(base, ko)                                                 \
        do {                                                                   \
            const uint32_t _d = (base) + ldoff;                                \
            CP_ASYNC16(_d + 128 * ROWB, pb + (ko));                            \
            CP_ASYNC16(_d + 160 * ROWB, pb + (ko) + (size_t)32 * DDIM);        \
            CP_ASYNC16(_d + 192 * ROWB, ab + (ko));                            \
            CP_ASYNC16(_d + 224 * ROWB, ab + (ko) + (size_t)32 * DDIM);        \
        } while (0)

    // ldmatrix lane mappings
    const int a_r = lane & 15;
    const int a_c = lane >> 4;
    const int b_r = (lane & 7) | ((lane & 16) >> 1);
    const int b_h = (lane >> 3) & 1;
    const uint32_t smA = (wm * 64 + a_r) * ROWB + a_c * 16;
    const uint32_t smP = (128 + wn * 16 + b_r) * ROWB + b_h * 16;
    const uint32_t smQ = (192 + wn * 16 + b_r) * ROWB + b_h * 16;
    const uint32_t kof0 = (rot & 3) * 32;

    float cP[4][2][4];
    float cA[4][2][4];
    #pragma unroll
    for (int mt = 0; mt < 4; mt++)
        #pragma unroll
        for (int nt = 0; nt < 2; nt++)
            #pragma unroll
            for (int i = 0; i < 4; i++) { cP[mt][nt][i] = 0.f; cA[mt][nt][i] = 0.f; }

    // pre-arm free[2]
    MB_ARRIVE(sb + 24 + 16);

    // prologue: stages 0 and 1; wait stage 0 and preload first B frags
    ISSUE_X(sb + STG0, 0);             ISSUE_PA(sb + STG0, 0);
    CPX_ARRIVE(sb + 0);
    ISSUE_X(sb + STG0 + STAGEB, BK);   ISSUE_PA(sb + STG0 + STAGEB, BK);
    CPX_ARRIVE(sb + 8);

    uint32_t bp[2][4], ba[2][4];
    MBARRIER_WAIT_PARITY(sb + 0, 0);
    LDSM4(bp[0], sb + STG0 + smP + kof0);
    LDSM4(ba[0], sb + STG0 + smQ + kof0);

    // One k-iteration; rolling 2-deep A buffer (xh), mt processed in halves.
    #define KITER(FS, IS, NS, KO2, DO_ISSUE, DO_NEXT, NPAR)                    \
    {                                                                          \
        const uint32_t st  = sb + STG0 + (FS) * STAGEB;                        \
        const uint32_t stn = sb + STG0 + (NS) * STAGEB;                        \
        _Pragma("unroll")                                                      \
        for (int ks = 0; ks < 4; ks++) {                                       \
            const int cur = ks & 1;                                            \
            const uint32_t kofs = ((ks + rot) & 3) * 32;                       \
            uint32_t xh[2][4];                                                 \
            LDSM4(xh[0], st + smA + kofs);                                     \
            LDSM4(xh[1], st + smA + 16 * ROWB + kofs);                         \
            if (ks < 3) {                                                      \
                const uint32_t knx = ((ks + 1 + rot) & 3) * 32;                \
                LDSM4(bp[cur ^ 1], st + smP + knx);                            \
                LDSM4(ba[cur ^ 1], st + smQ + knx);                            \
            }                                                                  \
            if ((DO_ISSUE) && ks == 1) {                                       \
                MBARRIER_WAIT_PARITY_RELAXED(sb + 24 + (IS) * 8, pm);          \
                ISSUE_X(sb + STG0 + (IS) * STAGEB, KO2);                       \
            }                                                                  \
            _Pragma("unroll")                                                  \
            for (int mt = 0; mt < 2; mt++) {                                   \
                _Pragma("unroll")                                              \
                for (int nt = 0; nt < 2; nt++) {                               \
                    MMA16816(cP[mt][nt], xh[mt], bp[cur][nt * 2], bp[cur][nt * 2 + 1]); \
                    MMA16816(cA[mt][nt], xh[mt], ba[cur][nt * 2], ba[cur][nt * 2 + 1]); \
                }                                                              \
            }                                                                  \
            LDSM4(xh[0], st + smA + 32 * ROWB + kofs);                         \
            LDSM4(xh[1], st + smA + 48 * ROWB + kofs);                         \
            if (ks == 3) MB_ARRIVE(sb + 24 + (FS) * 8);  /* stage FS free */   \
            if ((DO_ISSUE) && ks == 2) {                                       \
                ISSUE_PA(sb + STG0 + (IS) * STAGEB, KO2);                      \
                CPX_ARRIVE(sb + (IS) * 8);                                     \
            }                                                                  \
            if ((DO_NEXT) && ks == 2)                                          \
                MBARRIER_WAIT_PARITY(sb + (NS) * 8, NPAR);                     \
            if ((DO_NEXT) && ks == 3) {                                        \
                LDSM4(bp[0], stn + smP + kof0);                                \
                LDSM4(ba[0], stn + smQ + kof0);                                \
            }                                                                  \
            _Pragma("unroll")                                                  \
            for (int mt = 0; mt < 2; mt++) {                                   \
                _Pragma("unroll")                                              \
                for (int nt = 0; nt < 2; nt++) {                               \
                    MMA16816(cP[mt + 2][nt], xh[mt], bp[cur][nt * 2], bp[cur][nt * 2 + 1]); \
                    MMA16816(cA[mt + 2][nt], xh[mt], ba[cur][nt * 2], ba[cur][nt * 2 + 1]); \
                }                                                              \
            }                                                                  \
        }                                                                      \
    }

    uint32_t pm = 0;
    size_t kb = 0;
    #pragma unroll 1
    for (int m = 0; m < 5; m++) {      // k = 3m .. 3m+2 (k = 0..14)
        KITER(0, 2, 1, kb + 2 * BK, true, true, pm);
        KITER(1, 0, 2, kb + 3 * BK, true, true, pm);
        KITER(2, 1, 0, kb + 4 * BK, true, true, pm ^ 1);
        pm ^= 1;
        kb += 3 * BK;
    }
    KITER(0, 2, 1, 0, false, false, pm);   // k = 15

    // epilogue (registers only); hoist per-class and per-row scalars
    const int g  = lane >> 2;
    const int tg = lane & 3;
    const int colb = cb + wn * 16 + tg * 2;
    float p2c[4], pac[4], anc[4];
    #pragma unroll
    for (int nt = 0; nt < 2; nt++) {
        p2c[nt * 2]     = g_p2[colb + nt * 8];
        p2c[nt * 2 + 1] = g_p2[colb + nt * 8 + 1];
        pac[nt * 2]     = g_pa[colb + nt * 8];
        pac[nt * 2 + 1] = g_pa[colb + nt * 8 + 1];
        anc[nt * 2]     = g_an[colb + nt * 8];
        anc[nt * 2 + 1] = g_an[colb + nt * 8 + 1];
    }
    #pragma unroll
    for (int mt = 0; mt < 4; mt++) {
        #pragma unroll
        for (int h = 0; h < 2; h++) {
            const int row = rb + wm * 64 + mt * 16 + h * 8 + g;
            const float x2 = g_x2[row];
            float* orow = out + (size_t)row * CDIM + cb + wn * 16;
            #pragma unroll
            for (int nt = 0; nt < 2; nt++) {
                float2 r;
                r.x = hyp_logit(cP[mt][nt][2 * h],     cA[mt][nt][2 * h],     x2,
                                p2c[nt * 2],     pac[nt * 2],     anc[nt * 2]);
                r.y = hyp_logit(cP[mt][nt][2 * h + 1], cA[mt][nt][2 * h + 1], x2,
                                p2c[nt * 2 + 1], pac[nt * 2 + 1], anc[nt * 2 + 1]);
                *(float2*)(orow + nt * 8 + tg * 2) = r;
            }
        }
    }
    #undef KITER
    #undef ISSUE_X
    #undef ISSUE_PA
}

// ---------------------------------------------------------------------------
extern "C" void kernel_launch(void* const* d_in, const int* in_sizes, int n_in,
                              void* d_out, int out_size) {
    const float* x = (const float*)d_in[0];
    const float* a = (const float*)d_in[1];
    const float* p = (const float*)d_in[2];
    float* out = (float*)d_out;

    cudaFuncSetAttribute(mlr_mma_kernel,
                         cudaFuncAttributeMaxDynamicSharedMemorySize, SMEM_NEED);

    prep_kernel<<<BDIM + CDIM, 256>>>(x, a, p);
    dim3 grid(CDIM / BN, BDIM / BM);
    mlr_mma_kernel<<<grid, 256, SMEM_NEED>>>(out);
}